// round 3
// baseline (speedup 1.0000x reference)
#include <cuda_runtime.h>
#include <math.h>

#define NN 10000
#define EORIG 50000
#define EDOUB 100000
#define BB 4
#define NT 40000
#define DD 64
#define KS_N 4000u
#define ES_E 40000u

// ------------------------- device scratch (zero-initialized at load) ------
__device__ float g_hidden[NT * DD];
__device__ float g_score[NT];
__device__ float g_feat[NT * 256];
__device__ float g_C[NT * 192];
__device__ float g_Wcat[3 * 256 * 192];
__device__ float g_qpart[DD];
__device__ float g_deg[NT];
__device__ int   g_ptr[NN + 1];
__device__ int   g_cur[NN];
__device__ int   g_cnt[NN];
__device__ int   g_adj[EDOUB];
__device__ int   g_wlist[NT];
__device__ unsigned g_bins0[65536];
__device__ unsigned g_bins1[65536];
__device__ float g_pna;
__device__ float g_thr;   // node threshold (rank-4000 score)
__device__ float g_T;     // effective threshold for edge mask
__device__ unsigned g_digit, g_krem, g_skip;
__device__ int g_wl;
__device__ int g_ticket;  // zero-init; tails restore to 0

// ------------------------- helpers -------------------------
__device__ __forceinline__ unsigned f2key(float f) {
    unsigned u = __float_as_uint(f);
    return (u & 0x80000000u) ? ~u : (u | 0x80000000u);
}
__device__ __forceinline__ float key2f(unsigned key) {
    unsigned u = (key & 0x80000000u) ? (key & 0x7FFFFFFFu) : ~key;
    return __uint_as_float(u);
}

// warp-aggregated weighted histogram add (handles massive ties in layer 0)
__device__ __forceinline__ void warpHistAdd(unsigned* bins, unsigned bin, unsigned w) {
    unsigned m = __match_any_sync(0xffffffffu, bin);
    int lane = threadIdx.x & 31;
    int leader = __ffs(m) - 1;
    unsigned tot = 0;
    #pragma unroll
    for (int j = 0; j < 32; j++) {
        unsigned bj = __shfl_sync(0xffffffffu, bin, j);
        unsigned wj = __shfl_sync(0xffffffffu, w, j);
        if (bj == bin) tot += wj;
    }
    if (bin <= 0xFFFFu && lane == leader && tot > 0) atomicAdd(&bins[bin], tot);
}

// ------------------------- setup kernels -------------------------
__global__ void k_init() {
    int i = blockIdx.x * blockDim.x + threadIdx.x;
    if (i < NT) g_score[i] = 0.0f;
    if (i < NN) g_cnt[i] = 0;
}

__global__ void k_count(const int* __restrict__ ei) {
    int e = blockIdx.x * blockDim.x + threadIdx.x;
    if (e >= EDOUB) return;
    int dst = ei[(e + EORIG) % EDOUB];
    atomicAdd(&g_cnt[dst], 1);
}

__global__ void k_scan() {  // 1 block, 1024 threads
    __shared__ unsigned cs[1024];
    __shared__ float ps[1024];
    int t = threadIdx.x;
    unsigned loc[10];
    unsigned s = 0; float pl = 0.0f;
    #pragma unroll
    for (int i = 0; i < 10; i++) {
        int idx = t * 10 + i;
        unsigned c = (idx < NN) ? (unsigned)g_cnt[idx] : 0u;
        loc[i] = c; s += c;
        if (idx < NN) pl += logf((float)c + 1.0f);
    }
    cs[t] = s; ps[t] = pl;
    __syncthreads();
    for (int off = 1; off < 1024; off <<= 1) {
        unsigned v = (t >= off) ? cs[t - off] : 0u;
        __syncthreads();
        cs[t] += v;
        __syncthreads();
    }
    unsigned run = cs[t] - s;
    #pragma unroll
    for (int i = 0; i < 10; i++) {
        int idx = t * 10 + i;
        if (idx < NN) { g_ptr[idx] = (int)run; g_cur[idx] = (int)run; run += loc[i]; }
    }
    if (t == 1023) g_ptr[NN] = (int)cs[1023];
    for (int off = 512; off > 0; off >>= 1) {
        __syncthreads();
        if (t < off) ps[t] += ps[t + off];
    }
    __syncthreads();
    if (t == 0) g_pna = ps[0] / (float)NN;
}

__global__ void k_scatter(const int* __restrict__ ei, const int* __restrict__ ea) {
    int e = blockIdx.x * blockDim.x + threadIdx.x;
    if (e >= EDOUB) return;
    int src = ei[e];
    int dst = ei[(e + EORIG) % EDOUB];
    int a   = ea[e % EORIG];
    int pos = atomicAdd(&g_cur[dst], 1);
    g_adj[pos] = src | (a << 16);
}

__global__ void k_inithidden(const float* __restrict__ text,
                             const int* __restrict__ h_index,
                             const float* __restrict__ hstates) {
    int idx = blockIdx.x * blockDim.x + threadIdx.x;   // float4 index
    if (idx >= NT * 16) return;
    int v = idx >> 4, q = idx & 15;
    float4 val = make_float4(0, 0, 0, 0);
    if (v < NN) val = *(const float4*)(text + (size_t)v * DD + q * 4);
    int b = v / NN;
    int h0b = h_index[b * 16] + b * NN;
    if (v == h0b) val = *(const float4*)(hstates + b * DD + q * 4);
    *(float4*)(g_hidden + (size_t)v * DD + q * 4) = val;
}

__global__ void k_repack(const float* __restrict__ convW) {
    int idx = blockIdx.x * blockDim.x + threadIdx.x;
    if (idx >= 3 * 256 * 192) return;
    int l = idx / 49152;
    int rem = idx % 49152;
    int kk = rem / 192, j = rem % 192;
    int g = j >> 6, c = j & 63;
    g_Wcat[idx] = convW[(l * 768 + g * 256 + kk) * 64 + c];
}

__global__ void k_qpart(const int* __restrict__ r_index,
                        const float* __restrict__ relT,
                        const float* __restrict__ Wlin,
                        const float* __restrict__ blin) {
    int j = threadIdx.x;
    if (j >= DD) return;
    int r0 = r_index[0];
    float acc = blin[j];
    for (int d = 0; d < DD; d++)
        acc += relT[r0 * DD + d] * Wlin[(DD + d) * DD + j];
    g_qpart[j] = acc;
}

__global__ void k_headscore(const int* __restrict__ h_index,
                            const int* __restrict__ r_index,
                            const float* __restrict__ hstates,
                            const float* __restrict__ relT,
                            const float* __restrict__ Wlin,
                            const float* __restrict__ blin,
                            const float* __restrict__ W1,
                            const float* __restrict__ b1,
                            const float* __restrict__ W2,
                            const float* __restrict__ b2) {
    __shared__ float sx[4][64];
    int t = threadIdx.x;      // 128 threads = 4 warps
    int b = t >> 5, ln = t & 31;
    int r0 = r_index[b * 16];
    int h0b = h_index[b * 16] + b * NN;
    const float* hv = hstates + b * DD;
    const float* rv = relT + r0 * DD;
    #pragma unroll
    for (int half = 0; half < 2; half++) {
        int c = ln + half * 32;
        float acc = blin[c];
        for (int d = 0; d < DD; d++)
            acc += hv[d] * Wlin[d * DD + c] + rv[d] * Wlin[(DD + d) * DD + c];
        sx[b][c] = hv[c] * acc;
    }
    __syncwarp();
    float sp = 0.0f;
    #pragma unroll
    for (int oo = 0; oo < 4; oo++) {
        int o = ln * 4 + oo;
        float a2 = b1[o];
        for (int d = 0; d < DD; d++) a2 += sx[b][d] * W1[d * 128 + o];
        a2 = fmaxf(a2, 0.0f);
        sp += a2 * W2[o];
    }
    #pragma unroll
    for (int off = 16; off > 0; off >>= 1)
        sp += __shfl_down_sync(0xffffffffu, sp, off);
    if (ln == 0) g_score[h0b] = sp + b2[0];
}

// ------------------------- fused selection kernels -------------------------
// Pass A: histogram of high 16 key bits + tail-block picks digit.
__global__ void k_selA(int isEdge, unsigned kparam) {  // grid 157, block 256
    int i = blockIdx.x * blockDim.x + threadIdx.x;
    unsigned bin = 0x10000u, w = 0;
    float thr = g_thr;
    if (i < NT) {
        float sc = g_score[i];
        if (!isEdge || sc >= thr) {
            bin = f2key(sc) >> 16;
            if (isEdge) {
                int lv = i - (i / NN) * NN;
                w = (unsigned)(g_ptr[lv + 1] - g_ptr[lv]);
            } else w = 1;
        }
    }
    warpHistAdd(g_bins0, bin, w);
    __threadfence();
    __shared__ int lastf;
    if (threadIdx.x == 0) lastf = (atomicAdd(&g_ticket, 1) == (int)gridDim.x - 1);
    __syncthreads();
    if (!lastf) return;
    // ---- tail pick (256 threads, 256 bins each) ----
    int t = threadIdx.x;
    __shared__ unsigned ss[256];
    int base = t * 256;
    unsigned s = 0;
    #pragma unroll 8
    for (int j = 0; j < 256; j++) s += g_bins0[base + j];
    ss[t] = s;
    __syncthreads();
    for (int off = 1; off < 256; off <<= 1) {
        unsigned v = (t + off < 256) ? ss[t + off] : 0u;
        __syncthreads();
        ss[t] += v;
        __syncthreads();
    }
    unsigned total = ss[0];
    bool skip = false;
    if (isEdge) {
        if (total < kparam) {
            if (t == 0) { g_skip = 1; g_T = g_thr; }
            skip = true;
        } else if (t == 0) g_skip = 0;
    }
    if (!skip) {
        unsigned inc = ss[t], exc = inc - s;
        if (exc < kparam && inc >= kparam) {
            unsigned c = exc;
            for (int j = 255; j >= 0; j--) {
                unsigned bv = g_bins0[base + j];
                if (c + bv >= kparam) {
                    g_digit = (unsigned)(base + j);
                    g_krem = kparam - c;
                    break;
                }
                c += bv;
            }
        }
    }
    __syncthreads();
    #pragma unroll 8
    for (int j = 0; j < 256; j++) g_bins0[base + j] = 0;
    if (t == 0) g_ticket = 0;
}

// Pass B: histogram of low 16 bits within selected digit + tail picks value.
__global__ void k_selB(int isEdge) {  // grid 157, block 256
    int i = blockIdx.x * blockDim.x + threadIdx.x;
    unsigned bin = 0x10000u, w = 0;
    unsigned dig = g_digit;
    int skipk = isEdge && g_skip;
    float thr = g_thr;
    if (i < NT && !skipk) {
        float sc = g_score[i];
        if (!isEdge || sc >= thr) {
            unsigned key = f2key(sc);
            if ((key >> 16) == dig) {
                bin = key & 0xFFFFu;
                if (isEdge) {
                    int lv = i - (i / NN) * NN;
                    w = (unsigned)(g_ptr[lv + 1] - g_ptr[lv]);
                } else w = 1;
            }
        }
    }
    warpHistAdd(g_bins1, bin, w);
    __threadfence();
    __shared__ int lastf;
    if (threadIdx.x == 0) lastf = (atomicAdd(&g_ticket, 1) == (int)gridDim.x - 1);
    __syncthreads();
    if (!lastf) return;
    int t = threadIdx.x;
    if (skipk) {   // bins1 untouched (still zero); nothing to pick
        if (t == 0) { g_wl = 0; g_ticket = 0; }
        return;
    }
    __shared__ unsigned ss[256];
    int base = t * 256;
    unsigned s = 0;
    #pragma unroll 8
    for (int j = 0; j < 256; j++) s += g_bins1[base + j];
    ss[t] = s;
    __syncthreads();
    for (int off = 1; off < 256; off <<= 1) {
        unsigned v = (t + off < 256) ? ss[t + off] : 0u;
        __syncthreads();
        ss[t] += v;
        __syncthreads();
    }
    unsigned kk = g_krem;
    unsigned inc = ss[t], exc = inc - s;
    if (exc < kk && inc >= kk) {
        unsigned c = exc;
        for (int j = 255; j >= 0; j--) {
            unsigned bv = g_bins1[base + j];
            if (c + bv >= kk) {
                unsigned key = (dig << 16) | (unsigned)(base + j);
                float val = key2f(key);
                if (!isEdge) g_thr = val; else g_T = val;
                break;
            }
            c += bv;
        }
    }
    __syncthreads();
    #pragma unroll 8
    for (int j = 0; j < 256; j++) g_bins1[base + j] = 0;
    if (t == 0) { if (isEdge) g_wl = 0; g_ticket = 0; }
}

__global__ void k_worklist() {
    int i = blockIdx.x * blockDim.x + threadIdx.x;
    bool f = false;
    if (i < NT) {
        int lv = i - (i / NN) * NN;
        f = (g_score[i] >= g_T) && (g_ptr[lv + 1] > g_ptr[lv]);
    }
    unsigned m = __ballot_sync(0xffffffffu, f);
    if (m == 0) return;
    int lane = threadIdx.x & 31;
    int leader = __ffs(m) - 1;
    int pos = 0;
    if (lane == leader) pos = atomicAdd(&g_wl, __popc(m));
    pos = __shfl_sync(0xffffffffu, pos, leader);
    if (f) g_wlist[pos + __popc(m & ((1u << lane) - 1u))] = i;
}

// ------------------------- per-layer compute -------------------------
__global__ void k_agg(const float* __restrict__ relw, int l) {
    int w = blockIdx.x * 8 + (threadIdx.x >> 5);
    int cnt = g_wl;
    if (w >= cnt) return;
    int lane = threadIdx.x & 31;
    int v = g_wlist[w];
    int b = v / NN;
    int base = b * NN;
    int lv = v - base;
    int d0 = lane, d1 = lane + 32;
    const float* rw = relw + l * 400 * DD;
    float T = g_T;
    float s0 = 0, s1 = 0, q0 = 0, q1 = 0;
    float mx0 = -INFINITY, mx1 = -INFINITY, mn0 = INFINITY, mn1 = INFINITY;
    int deg = 0;
    int p1 = g_ptr[lv + 1];
    for (int p = g_ptr[lv]; p < p1; p++) {
        int pk = __ldg(&g_adj[p]);
        int u = pk & 0xFFFF, a = pk >> 16;
        int gu = base + u;
        float sc = g_score[gu];
        if (sc >= T) {
            float wgt = 1.0f / (1.0f + __expf(-sc));
            float m0 = wgt * g_hidden[gu * DD + d0] * rw[a * DD + d0];
            float m1 = wgt * g_hidden[gu * DD + d1] * rw[a * DD + d1];
            s0 += m0; q0 += m0 * m0; mx0 = fmaxf(mx0, m0); mn0 = fminf(mn0, m0);
            s1 += m1; q1 += m1 * m1; mx1 = fmaxf(mx1, m1); mn1 = fminf(mn1, m1);
            deg++;
        }
    }
    float fdeg = (float)deg;
    float den = fmaxf(fdeg, 1.0f);
    float me0 = s0 / den, me1 = s1 / den;
    float sd0 = sqrtf(fmaxf(q0 / den - me0 * me0, 0.0f) + 1e-6f);
    float sd1 = sqrtf(fmaxf(q1 / den - me1 * me1, 0.0f) + 1e-6f);
    if (deg == 0) { mx0 = 0; mx1 = 0; mn0 = 0; mn1 = 0; }
    float* F = g_feat + (size_t)w * 256;
    F[d0] = me0;        F[d1] = me1;
    F[64 + d0] = mx0;   F[64 + d1] = mx1;
    F[128 + d0] = mn0;  F[128 + d1] = mn1;
    F[192 + d0] = sd0;  F[192 + d1] = sd1;
    if (lane == 0) g_deg[w] = fdeg;
}

// C[cnt,192] = feat[cnt,256] @ Wcat[256,192]; 128x64 tile, 8x4 micro-tile
__global__ void k_gemm(int l) {
    __shared__ float sA[16 * 128];
    __shared__ float sB[16 * 64];
    int cnt = g_wl;
    int rowBase = blockIdx.x * 128;
    if (rowBase >= cnt) return;
    int colBase = blockIdx.y * 64;
    int t = threadIdx.x;
    int tx = t & 15, ty = t >> 4;
    const float* Wb = g_Wcat + l * 256 * 192;
    float acc[8][4] = {};
    for (int k0 = 0; k0 < 256; k0 += 16) {
        #pragma unroll
        for (int q = 0; q < 2; q++) {
            int lin = t * 2 + q;            // 0..511
            int r = lin >> 2, kq = lin & 3;
            float4 av = make_float4(0, 0, 0, 0);
            int row = rowBase + r;
            if (row < cnt) av = *(const float4*)(g_feat + (size_t)row * 256 + k0 + kq * 4);
            sA[(kq * 4 + 0) * 128 + r] = av.x;
            sA[(kq * 4 + 1) * 128 + r] = av.y;
            sA[(kq * 4 + 2) * 128 + r] = av.z;
            sA[(kq * 4 + 3) * 128 + r] = av.w;
        }
        {
            int kb = t >> 4, j4 = (t & 15) * 4;
            float4 bv = *(const float4*)(Wb + (size_t)(k0 + kb) * 192 + colBase + j4);
            *(float4*)&sB[kb * 64 + j4] = bv;
        }
        __syncthreads();
        #pragma unroll
        for (int kk = 0; kk < 16; kk++) {
            float4 a0 = *(float4*)&sA[kk * 128 + ty * 8];
            float4 a1 = *(float4*)&sA[kk * 128 + ty * 8 + 4];
            float4 b0 = *(float4*)&sB[kk * 64 + tx * 4];
            float a[8] = {a0.x, a0.y, a0.z, a0.w, a1.x, a1.y, a1.z, a1.w};
            float bb[4] = {b0.x, b0.y, b0.z, b0.w};
            #pragma unroll
            for (int i = 0; i < 8; i++)
                #pragma unroll
                for (int j = 0; j < 4; j++)
                    acc[i][j] += a[i] * bb[j];
        }
        __syncthreads();
    }
    #pragma unroll
    for (int i = 0; i < 8; i++) {
        int row = rowBase + ty * 8 + i;
        if (row < cnt) {
            float4 v = make_float4(acc[i][0], acc[i][1], acc[i][2], acc[i][3]);
            *(float4*)(g_C + (size_t)row * 192 + colBase + tx * 4) = v;
        }
    }
}

// Fused: hidden update (apply) + heuristic GEMM + score MLP. 64 rows/block.
// dynamic smem: sh[64*65] | sbuf[64*128] | sqp[64] samp[64] satt[64] sw2[128] sb1[128] sv[64]
__global__ void k_post(const float* __restrict__ convb,
                       const float* __restrict__ Wlin,
                       const float* __restrict__ W1,
                       const float* __restrict__ b1,
                       const float* __restrict__ W2,
                       const float* __restrict__ b2, int l) {
    extern __shared__ float smem[];
    float* sh   = smem;                       // 64*65
    float* sbuf = smem + 64 * 65;             // 64*128 (Wlin pitch 68, then W1 pitch 128)
    float* sqp  = sbuf + 64 * 128;
    float* samp = sqp + 64;
    float* satt = samp + 64;
    float* sw2  = satt + 64;
    float* sb1  = sw2 + 128;
    int*   sv   = (int*)(sb1 + 128);          // 64

    int cnt = g_wl;
    int rowBase = blockIdx.x * 64;
    if (rowBase >= cnt) return;
    int t = threadIdx.x;

    if (t < 64) {
        int i = rowBase + t;
        float dg = (i < cnt) ? g_deg[i] : 0.0f;
        float sl = logf(dg + 1.0f);
        float pna = g_pna;
        samp[t] = sl / pna;
        satt[t] = pna / (sl + 1e-6f);
        sv[t] = (i < cnt) ? g_wlist[i] : -1;
        sqp[t] = g_qpart[t];
    }
    if (t < 128) { sw2[t] = W2[t]; sb1[t] = b1[t]; }
    __syncthreads();

    // phase 0: hidden += relu(upd); keep new hidden in shared
    #pragma unroll
    for (int q = 0; q < 16; q++) {
        int lin = t + q * 256;
        int r = lin >> 6, d = lin & 63;
        int i = rowBase + r;
        float nh = 0.0f;
        if (i < cnt) {
            const float* C = g_C + (size_t)i * 192;
            float u = C[d] + samp[r] * C[64 + d] + satt[r] * C[128 + d] + convb[l * 64 + d];
            u = fmaxf(u, 0.0f);
            int v = sv[r];
            nh = g_hidden[v * DD + d] + u;
            g_hidden[v * DD + d] = nh;
        }
        sh[r * 65 + d] = nh;
    }
    // load Wlin[0:64][0:64] at pitch 68
    #pragma unroll
    for (int q = 0; q < 16; q++) {
        int lin = t + q * 256;
        int r = lin >> 6, c = lin & 63;
        sbuf[r * 68 + c] = Wlin[r * DD + c];
    }
    __syncthreads();

    // phase 1: heur = h @ Wlin0 + qpart; x = h * heur (overwrite sh)
    int tx = t & 15, ty = t >> 4;
    {
        float acc[4][4] = {};
        for (int k = 0; k < 64; k++) {
            float a[4], bb[4];
            #pragma unroll
            for (int i = 0; i < 4; i++) a[i] = sh[(ty * 4 + i) * 65 + k];
            float4 b4 = *(float4*)&sbuf[k * 68 + tx * 4];
            bb[0] = b4.x; bb[1] = b4.y; bb[2] = b4.z; bb[3] = b4.w;
            #pragma unroll
            for (int i = 0; i < 4; i++)
                #pragma unroll
                for (int j = 0; j < 4; j++)
                    acc[i][j] += a[i] * bb[j];
        }
        __syncthreads();
        #pragma unroll
        for (int i = 0; i < 4; i++)
            #pragma unroll
            for (int j = 0; j < 4; j++) {
                int r = ty * 4 + i, c = tx * 4 + j;
                float hv = sh[r * 65 + c];
                sh[r * 65 + c] = hv * (acc[i][j] + sqp[c]);
            }
        __syncthreads();
    }

    // load W1 [64][128] into sbuf (pitch 128)
    #pragma unroll
    for (int q = 0; q < 32; q++) {
        int lin = t + q * 256;
        sbuf[lin] = W1[lin];
    }
    __syncthreads();

    // phase 2: t1 = relu(x @ W1 + b1); score = t1 @ W2 + b2
    {
        float acc[4][8] = {};
        for (int k = 0; k < 64; k++) {
            float a[4];
            #pragma unroll
            for (int i = 0; i < 4; i++) a[i] = sh[(ty * 4 + i) * 65 + k];
            float4 b0 = *(float4*)&sbuf[k * 128 + tx * 8];
            float4 b1v = *(float4*)&sbuf[k * 128 + tx * 8 + 4];
            float bb[8] = {b0.x, b0.y, b0.z, b0.w, b1v.x, b1v.y, b1v.z, b1v.w};
            #pragma unroll
            for (int i = 0; i < 4; i++)
                #pragma unroll
                for (int j = 0; j < 8; j++)
                    acc[i][j] += a[i] * bb[j];
        }
        float bias2 = b2[0];
        #pragma unroll
        for (int i = 0; i < 4; i++) {
            float p = 0.0f;
            #pragma unroll
            for (int j = 0; j < 8; j++) {
                int o = tx * 8 + j;
                p += fmaxf(acc[i][j] + sb1[o], 0.0f) * sw2[o];
            }
            p += __shfl_xor_sync(0xffffffffu, p, 1);
            p += __shfl_xor_sync(0xffffffffu, p, 2);
            p += __shfl_xor_sync(0xffffffffu, p, 4);
            p += __shfl_xor_sync(0xffffffffu, p, 8);
            if ((t & 15) == 0) {
                int i2 = rowBase + ty * 4 + i;
                if (i2 < cnt) {
                    int v = sv[ty * 4 + i];
                    g_score[v] = p + bias2;
                }
            }
        }
    }
}

__global__ void k_out(const int* __restrict__ t_index, float* __restrict__ out) {
    int t = threadIdx.x;
    if (t >= 64) return;
    int b = t / 16;
    int v = t_index[t] + b * NN;
    out[t] = g_score[v];
}

// ------------------------- launch -------------------------
extern "C" void kernel_launch(void* const* d_in, const int* in_sizes, int n_in,
                              void* d_out, int out_size) {
    const int*   h_index   = (const int*)d_in[0];
    const int*   r_index   = (const int*)d_in[1];
    const int*   t_index   = (const int*)d_in[2];
    const float* hstates   = (const float*)d_in[3];
    const int*   edge_idx  = (const int*)d_in[5];
    const int*   edge_attr = (const int*)d_in[6];
    const float* text      = (const float*)d_in[7];
    const float* relT      = (const float*)d_in[9];
    const float* Wlin      = (const float*)d_in[10];
    const float* blin      = (const float*)d_in[11];
    const float* W1        = (const float*)d_in[12];
    const float* b1        = (const float*)d_in[13];
    const float* W2        = (const float*)d_in[14];
    const float* b2        = (const float*)d_in[15];
    const float* relw      = (const float*)d_in[16];
    const float* convW     = (const float*)d_in[17];
    const float* convb     = (const float*)d_in[18];
    float* out = (float*)d_out;

    const int SMEM_POST = (64 * 65 + 64 * 128 + 64 + 64 + 64 + 128 + 128 + 64) * 4;
    static int attr_done = 0;
    if (!attr_done) {
        cudaFuncSetAttribute(k_post, cudaFuncAttributeMaxDynamicSharedMemorySize, SMEM_POST);
        attr_done = 1;
    }

    k_init<<<157, 256>>>();
    k_count<<<391, 256>>>(edge_idx);
    k_scan<<<1, 1024>>>();
    k_scatter<<<391, 256>>>(edge_idx, edge_attr);
    k_inithidden<<<2500, 256>>>(text, h_index, hstates);
    k_repack<<<576, 256>>>(convW);
    k_qpart<<<1, 64>>>(r_index, relT, Wlin, blin);
    k_headscore<<<1, 128>>>(h_index, r_index, hstates, relT, Wlin, blin, W1, b1, W2, b2);

    for (int l = 0; l < 3; l++) {
        k_selA<<<157, 256>>>(0, KS_N);
        k_selB<<<157, 256>>>(0);
        k_selA<<<157, 256>>>(1, ES_E);
        k_selB<<<157, 256>>>(1);
        k_worklist<<<157, 256>>>();
        k_agg<<<5000, 256>>>(relw, l);
        k_gemm<<<dim3(313, 3), 256>>>(l);
        k_post<<<625, 256, SMEM_POST>>>(convb, Wlin, W1, b1, W2, b2, l);
    }
    k_out<<<1, 64>>>(t_index, out);
}

// round 4
// speedup vs baseline: 2.4553x; 2.4553x over previous
#include <cuda_runtime.h>
#include <math.h>

#define NN 10000
#define EORIG 50000
#define EDOUB 100000
#define BB 4
#define NT 40000
#define DD 64
#define KS_N 4000u
#define ES_E 40000u

// ------------------------- device scratch (zero-initialized at load) ------
__device__ float g_hidden[NT * DD];
__device__ float g_score[NT];
__device__ float g_feat[NT * 256];
__device__ float g_C[NT * 192];
__device__ float g_Wcat[3 * 256 * 192];
__device__ float g_qpart[DD];
__device__ float g_deg[NT];
__device__ int   g_ptr[NN + 1];
__device__ int   g_cur[NN];
__device__ int   g_cnt[NN];
__device__ int   g_adj[EDOUB];
__device__ int   g_wlist[NT];
__device__ unsigned g_binsA[2048];
__device__ float g_pna;
__device__ float g_thr;   // node threshold (rank-4000 score)
__device__ float g_T;     // effective threshold for edge mask
__device__ unsigned g_prefix, g_krem, g_skip;
__device__ int g_wl;
__device__ int g_ticket;  // zero-init; tails restore to 0

// ------------------------- helpers -------------------------
__device__ __forceinline__ unsigned f2key(float f) {
    unsigned u = __float_as_uint(f);
    return (u & 0x80000000u) ? ~u : (u | 0x80000000u);
}
__device__ __forceinline__ float key2f(unsigned key) {
    unsigned u = (key & 0x80000000u) ? (key & 0x7FFFFFFFu) : ~key;
    return __uint_as_float(u);
}

// warp-aggregated weighted histogram add (handles massive ties in layer 0)
__device__ __forceinline__ void warpHistAdd(unsigned* bins, unsigned bin, unsigned w, unsigned NBIG) {
    unsigned m = __match_any_sync(0xffffffffu, bin);
    int lane = threadIdx.x & 31;
    int leader = __ffs(m) - 1;
    unsigned tot = 0;
    #pragma unroll
    for (int j = 0; j < 32; j++) {
        unsigned bj = __shfl_sync(0xffffffffu, bin, j);
        unsigned wj = __shfl_sync(0xffffffffu, w, j);
        if (bj == bin) tot += wj;
    }
    if (bin < NBIG && lane == leader && tot > 0) atomicAdd(&bins[bin], tot);
}

// ------------------------- setup kernels -------------------------
__global__ void k_init() {
    int i = blockIdx.x * blockDim.x + threadIdx.x;
    if (i < NT) g_score[i] = 0.0f;
    if (i < NN) g_cnt[i] = 0;
}

__global__ void k_count(const int* __restrict__ ei) {
    int e = blockIdx.x * blockDim.x + threadIdx.x;
    if (e >= EDOUB) return;
    int dst = ei[(e + EORIG) % EDOUB];
    atomicAdd(&g_cnt[dst], 1);
}

__global__ void k_scan() {  // 1 block, 1024 threads
    __shared__ unsigned cs[1024];
    __shared__ float ps[1024];
    int t = threadIdx.x;
    unsigned loc[10];
    unsigned s = 0; float pl = 0.0f;
    #pragma unroll
    for (int i = 0; i < 10; i++) {
        int idx = t * 10 + i;
        unsigned c = (idx < NN) ? (unsigned)g_cnt[idx] : 0u;
        loc[i] = c; s += c;
        if (idx < NN) pl += logf((float)c + 1.0f);
    }
    cs[t] = s; ps[t] = pl;
    __syncthreads();
    for (int off = 1; off < 1024; off <<= 1) {
        unsigned v = (t >= off) ? cs[t - off] : 0u;
        __syncthreads();
        cs[t] += v;
        __syncthreads();
    }
    unsigned run = cs[t] - s;
    #pragma unroll
    for (int i = 0; i < 10; i++) {
        int idx = t * 10 + i;
        if (idx < NN) { g_ptr[idx] = (int)run; g_cur[idx] = (int)run; run += loc[i]; }
    }
    if (t == 1023) g_ptr[NN] = (int)cs[1023];
    for (int off = 512; off > 0; off >>= 1) {
        __syncthreads();
        if (t < off) ps[t] += ps[t + off];
    }
    __syncthreads();
    if (t == 0) g_pna = ps[0] / (float)NN;
}

__global__ void k_scatter(const int* __restrict__ ei, const int* __restrict__ ea) {
    int e = blockIdx.x * blockDim.x + threadIdx.x;
    if (e >= EDOUB) return;
    int src = ei[e];
    int dst = ei[(e + EORIG) % EDOUB];
    int a   = ea[e % EORIG];
    int pos = atomicAdd(&g_cur[dst], 1);
    g_adj[pos] = src | (a << 16);
}

__global__ void k_inithidden(const float* __restrict__ text,
                             const int* __restrict__ h_index,
                             const float* __restrict__ hstates) {
    int idx = blockIdx.x * blockDim.x + threadIdx.x;   // float4 index
    if (idx >= NT * 16) return;
    int v = idx >> 4, q = idx & 15;
    float4 val = make_float4(0, 0, 0, 0);
    if (v < NN) val = *(const float4*)(text + (size_t)v * DD + q * 4);
    int b = v / NN;
    int h0b = h_index[b * 16] + b * NN;
    if (v == h0b) val = *(const float4*)(hstates + b * DD + q * 4);
    *(float4*)(g_hidden + (size_t)v * DD + q * 4) = val;
}

__global__ void k_repack(const float* __restrict__ convW) {
    int idx = blockIdx.x * blockDim.x + threadIdx.x;
    if (idx >= 3 * 256 * 192) return;
    int l = idx / 49152;
    int rem = idx % 49152;
    int kk = rem / 192, j = rem % 192;
    int g = j >> 6, c = j & 63;
    g_Wcat[idx] = convW[(l * 768 + g * 256 + kk) * 64 + c];
}

__global__ void k_qpart(const int* __restrict__ r_index,
                        const float* __restrict__ relT,
                        const float* __restrict__ Wlin,
                        const float* __restrict__ blin) {
    int j = threadIdx.x;
    if (j >= DD) return;
    int r0 = r_index[0];
    float acc = blin[j];
    for (int d = 0; d < DD; d++)
        acc += relT[r0 * DD + d] * Wlin[(DD + d) * DD + j];
    g_qpart[j] = acc;
}

__global__ void k_headscore(const int* __restrict__ h_index,
                            const int* __restrict__ r_index,
                            const float* __restrict__ hstates,
                            const float* __restrict__ relT,
                            const float* __restrict__ Wlin,
                            const float* __restrict__ blin,
                            const float* __restrict__ W1,
                            const float* __restrict__ b1,
                            const float* __restrict__ W2,
                            const float* __restrict__ b2) {
    __shared__ float sx[4][64];
    int t = threadIdx.x;      // 128 threads = 4 warps
    int b = t >> 5, ln = t & 31;
    int r0 = r_index[b * 16];
    int h0b = h_index[b * 16] + b * NN;
    const float* hv = hstates + b * DD;
    const float* rv = relT + r0 * DD;
    #pragma unroll
    for (int half = 0; half < 2; half++) {
        int c = ln + half * 32;
        float acc = blin[c];
        for (int d = 0; d < DD; d++)
            acc += hv[d] * Wlin[d * DD + c] + rv[d] * Wlin[(DD + d) * DD + c];
        sx[b][c] = hv[c] * acc;
    }
    __syncwarp();
    float sp = 0.0f;
    #pragma unroll
    for (int oo = 0; oo < 4; oo++) {
        int o = ln * 4 + oo;
        float a2 = b1[o];
        for (int d = 0; d < DD; d++) a2 += sx[b][d] * W1[d * 128 + o];
        a2 = fmaxf(a2, 0.0f);
        sp += a2 * W2[o];
    }
    #pragma unroll
    for (int off = 16; off > 0; off >>= 1)
        sp += __shfl_down_sync(0xffffffffu, sp, off);
    if (ln == 0) g_score[h0b] = sp + b2[0];
}

// ------------------------- 3-pass radix select -------------------------
// pass 0: bits 31..21 (2048 bins); pass 1: bits 20..10 (2048); pass 2: bits 9..0 (1024)
// isEdge: filter score>=g_thr, weight = static in-degree; else weight 1.
__global__ void k_sel(int pass, int isEdge, unsigned kparam) {  // grid 157, block 256
    const int shift = (pass == 0) ? 21 : (pass == 1) ? 10 : 0;
    const unsigned nb = (pass == 2) ? 1024u : 2048u;
    int i = blockIdx.x * blockDim.x + threadIdx.x;
    unsigned prefix = (pass > 0) ? g_prefix : 0u;
    int skipk = (isEdge && pass > 0 && g_skip);
    float thr = g_thr;
    unsigned bin = 0xFFFFFFFFu, w = 0;
    if (i < NT && !skipk) {
        float sc = g_score[i];
        if (!isEdge || sc >= thr) {
            unsigned key = f2key(sc);
            bool match = (pass == 0) ||
                         (pass == 1 && (key >> 21) == (prefix >> 21)) ||
                         (pass == 2 && (key >> 10) == (prefix >> 10));
            if (match) {
                bin = (key >> shift) & (nb - 1u);
                if (isEdge) {
                    int lv = i - (i / NN) * NN;
                    w = (unsigned)(g_ptr[lv + 1] - g_ptr[lv]);
                } else w = 1;
            }
        }
    }
    warpHistAdd(g_binsA, bin, w, nb);
    __threadfence();
    __shared__ int lastf;
    if (threadIdx.x == 0) lastf = (atomicAdd(&g_ticket, 1) == (int)gridDim.x - 1);
    __syncthreads();
    if (!lastf) return;
    // ---- tail: suffix-sum pick over <=2048 bins ----
    int t = threadIdx.x;
    if (skipk) {
        if (t == 0) { g_ticket = 0; if (pass == 2) g_wl = 0; }
        return;
    }
    __shared__ unsigned ss[256];
    const int chunk = (int)(nb >> 8);     // 8 or 4
    unsigned loc[8];
    unsigned s = 0;
    #pragma unroll
    for (int j = 0; j < 8; j++) {
        loc[j] = (j < chunk) ? g_binsA[t * chunk + j] : 0u;
        s += loc[j];
    }
    ss[t] = s;
    __syncthreads();
    for (int off = 1; off < 256; off <<= 1) {   // suffix sums
        unsigned v = (t + off < 256) ? ss[t + off] : 0u;
        __syncthreads();
        ss[t] += v;
        __syncthreads();
    }
    unsigned total = ss[0];
    unsigned kk = (pass == 0) ? kparam : g_krem;
    bool skip = false;
    if (isEdge && pass == 0) {
        if (total < kparam) {
            if (t == 0) { g_skip = 1; g_T = g_thr; }
            skip = true;
        } else if (t == 0) g_skip = 0;
    }
    if (!skip) {
        unsigned cumTop = (t < 255) ? ss[t + 1] : 0u;   // weight strictly above my chunk
        if (cumTop < kk && cumTop + s >= kk) {
            unsigned c = cumTop;
            for (int j = chunk - 1; j >= 0; j--) {
                if (c + loc[j] >= kk) {
                    unsigned binidx = (unsigned)(t * chunk + j);
                    unsigned npref = prefix | (binidx << shift);
                    if (pass < 2) { g_prefix = npref; g_krem = kk - c; }
                    else {
                        float val = key2f(npref);
                        if (!isEdge) g_thr = val; else g_T = val;
                    }
                    break;
                }
                c += loc[j];
            }
        }
    }
    __syncthreads();
    #pragma unroll
    for (int j = 0; j < 8; j++)
        if (j < chunk) g_binsA[t * chunk + j] = 0;
    if (t == 0) { g_ticket = 0; if (pass == 2 && isEdge) g_wl = 0; }
}

__global__ void k_worklist() {
    int i = blockIdx.x * blockDim.x + threadIdx.x;
    bool f = false;
    if (i < NT) {
        int lv = i - (i / NN) * NN;
        f = (g_score[i] >= g_T) && (g_ptr[lv + 1] > g_ptr[lv]);
    }
    unsigned m = __ballot_sync(0xffffffffu, f);
    if (m == 0) return;
    int lane = threadIdx.x & 31;
    int leader = __ffs(m) - 1;
    int pos = 0;
    if (lane == leader) pos = atomicAdd(&g_wl, __popc(m));
    pos = __shfl_sync(0xffffffffu, pos, leader);
    if (f) g_wlist[pos + __popc(m & ((1u << lane) - 1u))] = i;
}

// ------------------------- per-layer compute -------------------------
__global__ void k_agg(const float* __restrict__ relw, int l) {
    int w = blockIdx.x * 8 + (threadIdx.x >> 5);
    int cnt = g_wl;
    if (w >= cnt) return;
    int lane = threadIdx.x & 31;
    int v = g_wlist[w];
    int b = v / NN;
    int base = b * NN;
    int lv = v - base;
    int d0 = lane, d1 = lane + 32;
    const float* rw = relw + l * 400 * DD;
    float T = g_T;
    float s0 = 0, s1 = 0, q0 = 0, q1 = 0;
    float mx0 = -INFINITY, mx1 = -INFINITY, mn0 = INFINITY, mn1 = INFINITY;
    int deg = 0;
    int p1 = g_ptr[lv + 1];
    for (int p = g_ptr[lv]; p < p1; p++) {
        int pk = __ldg(&g_adj[p]);
        int u = pk & 0xFFFF, a = pk >> 16;
        int gu = base + u;
        float sc = g_score[gu];
        if (sc >= T) {
            float wgt = 1.0f / (1.0f + __expf(-sc));
            float m0 = wgt * g_hidden[gu * DD + d0] * rw[a * DD + d0];
            float m1 = wgt * g_hidden[gu * DD + d1] * rw[a * DD + d1];
            s0 += m0; q0 += m0 * m0; mx0 = fmaxf(mx0, m0); mn0 = fminf(mn0, m0);
            s1 += m1; q1 += m1 * m1; mx1 = fmaxf(mx1, m1); mn1 = fminf(mn1, m1);
            deg++;
        }
    }
    float fdeg = (float)deg;
    float den = fmaxf(fdeg, 1.0f);
    float me0 = s0 / den, me1 = s1 / den;
    float sd0 = sqrtf(fmaxf(q0 / den - me0 * me0, 0.0f) + 1e-6f);
    float sd1 = sqrtf(fmaxf(q1 / den - me1 * me1, 0.0f) + 1e-6f);
    if (deg == 0) { mx0 = 0; mx1 = 0; mn0 = 0; mn1 = 0; }
    float* F = g_feat + (size_t)w * 256;
    F[d0] = me0;        F[d1] = me1;
    F[64 + d0] = mx0;   F[64 + d1] = mx1;
    F[128 + d0] = mn0;  F[128 + d1] = mn1;
    F[192 + d0] = sd0;  F[192 + d1] = sd1;
    if (lane == 0) g_deg[w] = fdeg;
}

// C[cnt,192] = feat[cnt,256] @ Wcat[256,192]; 128x64 tile, 8x4 micro-tile
__global__ void k_gemm(int l) {
    __shared__ float sA[16 * 128];
    __shared__ float sB[16 * 64];
    int cnt = g_wl;
    int rowBase = blockIdx.x * 128;
    if (rowBase >= cnt) return;
    int colBase = blockIdx.y * 64;
    int t = threadIdx.x;
    int tx = t & 15, ty = t >> 4;
    const float* Wb = g_Wcat + l * 256 * 192;
    float acc[8][4] = {};
    for (int k0 = 0; k0 < 256; k0 += 16) {
        #pragma unroll
        for (int q = 0; q < 2; q++) {
            int lin = t * 2 + q;            // 0..511
            int r = lin >> 2, kq = lin & 3;
            float4 av = make_float4(0, 0, 0, 0);
            int row = rowBase + r;
            if (row < cnt) av = *(const float4*)(g_feat + (size_t)row * 256 + k0 + kq * 4);
            sA[(kq * 4 + 0) * 128 + r] = av.x;
            sA[(kq * 4 + 1) * 128 + r] = av.y;
            sA[(kq * 4 + 2) * 128 + r] = av.z;
            sA[(kq * 4 + 3) * 128 + r] = av.w;
        }
        {
            int kb = t >> 4, j4 = (t & 15) * 4;
            float4 bv = *(const float4*)(Wb + (size_t)(k0 + kb) * 192 + colBase + j4);
            *(float4*)&sB[kb * 64 + j4] = bv;
        }
        __syncthreads();
        #pragma unroll
        for (int kk = 0; kk < 16; kk++) {
            float4 a0 = *(float4*)&sA[kk * 128 + ty * 8];
            float4 a1 = *(float4*)&sA[kk * 128 + ty * 8 + 4];
            float4 b0 = *(float4*)&sB[kk * 64 + tx * 4];
            float a[8] = {a0.x, a0.y, a0.z, a0.w, a1.x, a1.y, a1.z, a1.w};
            float bb[4] = {b0.x, b0.y, b0.z, b0.w};
            #pragma unroll
            for (int i = 0; i < 8; i++)
                #pragma unroll
                for (int j = 0; j < 4; j++)
                    acc[i][j] += a[i] * bb[j];
        }
        __syncthreads();
    }
    #pragma unroll
    for (int i = 0; i < 8; i++) {
        int row = rowBase + ty * 8 + i;
        if (row < cnt) {
            float4 v = make_float4(acc[i][0], acc[i][1], acc[i][2], acc[i][3]);
            *(float4*)(g_C + (size_t)row * 192 + colBase + tx * 4) = v;
        }
    }
}

// Fused: hidden update (apply) + heuristic GEMM + score MLP. 64 rows/block.
__global__ void k_post(const float* __restrict__ convb,
                       const float* __restrict__ Wlin,
                       const float* __restrict__ W1,
                       const float* __restrict__ b1,
                       const float* __restrict__ W2,
                       const float* __restrict__ b2, int l) {
    extern __shared__ float smem[];
    float* sh   = smem;                       // 64*65
    float* sbuf = smem + 64 * 65;             // 64*128 (Wlin pitch 68, then W1 pitch 128)
    float* sqp  = sbuf + 64 * 128;
    float* samp = sqp + 64;
    float* satt = samp + 64;
    float* sw2  = satt + 64;
    float* sb1  = sw2 + 128;
    int*   sv   = (int*)(sb1 + 128);          // 64

    int cnt = g_wl;
    int rowBase = blockIdx.x * 64;
    if (rowBase >= cnt) return;
    int t = threadIdx.x;

    if (t < 64) {
        int i = rowBase + t;
        float dg = (i < cnt) ? g_deg[i] : 0.0f;
        float sl = logf(dg + 1.0f);
        float pna = g_pna;
        samp[t] = sl / pna;
        satt[t] = pna / (sl + 1e-6f);
        sv[t] = (i < cnt) ? g_wlist[i] : -1;
        sqp[t] = g_qpart[t];
    }
    if (t < 128) { sw2[t] = W2[t]; sb1[t] = b1[t]; }
    __syncthreads();

    // phase 0: hidden += relu(upd); keep new hidden in shared
    #pragma unroll
    for (int q = 0; q < 16; q++) {
        int lin = t + q * 256;
        int r = lin >> 6, d = lin & 63;
        int i = rowBase + r;
        float nh = 0.0f;
        if (i < cnt) {
            const float* C = g_C + (size_t)i * 192;
            float u = C[d] + samp[r] * C[64 + d] + satt[r] * C[128 + d] + convb[l * 64 + d];
            u = fmaxf(u, 0.0f);
            int v = sv[r];
            nh = g_hidden[v * DD + d] + u;
            g_hidden[v * DD + d] = nh;
        }
        sh[r * 65 + d] = nh;
    }
    #pragma unroll
    for (int q = 0; q < 16; q++) {
        int lin = t + q * 256;
        int r = lin >> 6, c = lin & 63;
        sbuf[r * 68 + c] = Wlin[r * DD + c];
    }
    __syncthreads();

    // phase 1: heur = h @ Wlin0 + qpart; x = h * heur (overwrite sh)
    int tx = t & 15, ty = t >> 4;
    {
        float acc[4][4] = {};
        for (int k = 0; k < 64; k++) {
            float a[4], bb[4];
            #pragma unroll
            for (int i = 0; i < 4; i++) a[i] = sh[(ty * 4 + i) * 65 + k];
            float4 b4 = *(float4*)&sbuf[k * 68 + tx * 4];
            bb[0] = b4.x; bb[1] = b4.y; bb[2] = b4.z; bb[3] = b4.w;
            #pragma unroll
            for (int i = 0; i < 4; i++)
                #pragma unroll
                for (int j = 0; j < 4; j++)
                    acc[i][j] += a[i] * bb[j];
        }
        __syncthreads();
        #pragma unroll
        for (int i = 0; i < 4; i++)
            #pragma unroll
            for (int j = 0; j < 4; j++) {
                int r = ty * 4 + i, c = tx * 4 + j;
                float hv = sh[r * 65 + c];
                sh[r * 65 + c] = hv * (acc[i][j] + sqp[c]);
            }
        __syncthreads();
    }

    #pragma unroll
    for (int q = 0; q < 32; q++) {
        int lin = t + q * 256;
        sbuf[lin] = W1[lin];
    }
    __syncthreads();

    // phase 2: t1 = relu(x @ W1 + b1); score = t1 @ W2 + b2
    {
        float acc[4][8] = {};
        for (int k = 0; k < 64; k++) {
            float a[4];
            #pragma unroll
            for (int i = 0; i < 4; i++) a[i] = sh[(ty * 4 + i) * 65 + k];
            float4 b0 = *(float4*)&sbuf[k * 128 + tx * 8];
            float4 b1v = *(float4*)&sbuf[k * 128 + tx * 8 + 4];
            float bb[8] = {b0.x, b0.y, b0.z, b0.w, b1v.x, b1v.y, b1v.z, b1v.w};
            #pragma unroll
            for (int i = 0; i < 4; i++)
                #pragma unroll
                for (int j = 0; j < 8; j++)
                    acc[i][j] += a[i] * bb[j];
        }
        float bias2 = b2[0];
        #pragma unroll
        for (int i = 0; i < 4; i++) {
            float p = 0.0f;
            #pragma unroll
            for (int j = 0; j < 8; j++) {
                int o = tx * 8 + j;
                p += fmaxf(acc[i][j] + sb1[o], 0.0f) * sw2[o];
            }
            p += __shfl_xor_sync(0xffffffffu, p, 1);
            p += __shfl_xor_sync(0xffffffffu, p, 2);
            p += __shfl_xor_sync(0xffffffffu, p, 4);
            p += __shfl_xor_sync(0xffffffffu, p, 8);
            if ((t & 15) == 0) {
                int i2 = rowBase + ty * 4 + i;
                if (i2 < cnt) {
                    int v = sv[ty * 4 + i];
                    g_score[v] = p + bias2;
                }
            }
        }
    }
}

__global__ void k_out(const int* __restrict__ t_index, float* __restrict__ out) {
    int t = threadIdx.x;
    if (t >= 64) return;
    int b = t / 16;
    int v = t_index[t] + b * NN;
    out[t] = g_score[v];
}

// ------------------------- launch -------------------------
extern "C" void kernel_launch(void* const* d_in, const int* in_sizes, int n_in,
                              void* d_out, int out_size) {
    const int*   h_index   = (const int*)d_in[0];
    const int*   r_index   = (const int*)d_in[1];
    const int*   t_index   = (const int*)d_in[2];
    const float* hstates   = (const float*)d_in[3];
    const int*   edge_idx  = (const int*)d_in[5];
    const int*   edge_attr = (const int*)d_in[6];
    const float* text      = (const float*)d_in[7];
    const float* relT      = (const float*)d_in[9];
    const float* Wlin      = (const float*)d_in[10];
    const float* blin      = (const float*)d_in[11];
    const float* W1        = (const float*)d_in[12];
    const float* b1        = (const float*)d_in[13];
    const float* W2        = (const float*)d_in[14];
    const float* b2        = (const float*)d_in[15];
    const float* relw      = (const float*)d_in[16];
    const float* convW     = (const float*)d_in[17];
    const float* convb     = (const float*)d_in[18];
    float* out = (float*)d_out;

    const int SMEM_POST = (64 * 65 + 64 * 128 + 64 + 64 + 64 + 128 + 128 + 64) * 4;
    static int attr_done = 0;
    if (!attr_done) {
        cudaFuncSetAttribute(k_post, cudaFuncAttributeMaxDynamicSharedMemorySize, SMEM_POST);
        attr_done = 1;
    }

    k_init<<<157, 256>>>();
    k_count<<<391, 256>>>(edge_idx);
    k_scan<<<1, 1024>>>();
    k_scatter<<<391, 256>>>(edge_idx, edge_attr);
    k_inithidden<<<2500, 256>>>(text, h_index, hstates);
    k_repack<<<576, 256>>>(convW);
    k_qpart<<<1, 64>>>(r_index, relT, Wlin, blin);
    k_headscore<<<1, 128>>>(h_index, r_index, hstates, relT, Wlin, blin, W1, b1, W2, b2);

    for (int l = 0; l < 3; l++) {
        // node threshold (rank-4000): 3 radix passes
        k_sel<<<157, 256>>>(0, 0, KS_N);
        k_sel<<<157, 256>>>(1, 0, KS_N);
        k_sel<<<157, 256>>>(2, 0, KS_N);
        // edge threshold (weighted rank-40000 over active nodes): 3 passes
        k_sel<<<157, 256>>>(0, 1, ES_E);
        k_sel<<<157, 256>>>(1, 1, ES_E);
        k_sel<<<157, 256>>>(2, 1, ES_E);   // tail also resets g_wl
        // worklist of omask nodes, then aggregate/GEMM/post
        k_worklist<<<157, 256>>>();
        k_agg<<<5000, 256>>>(relw, l);
        k_gemm<<<dim3(313, 3), 256>>>(l);
        k_post<<<625, 256, SMEM_POST>>>(convb, Wlin, W1, b1, W2, b2, l);
    }
    k_out<<<1, 64>>>(t_index, out);
}

// round 6
// speedup vs baseline: 4.1054x; 1.6721x over previous
#include <cuda_runtime.h>
#include <math.h>

#define NN 10000
#define EORIG 50000
#define EDOUB 100000
#define BB 4
#define NT 40000
#define DD 64
#define KS_N 4000u
#define ES_E 40000u

// ------------------------- device scratch (zero-initialized at load) ------
__device__ float g_hidden[NT * DD];
__device__ float g_score[NT];
__device__ float g_feat[NT * 256];
__device__ float g_C[NT * 192];
__device__ float g_Wcat[3 * 256 * 192];
__device__ float g_qpart[DD];
__device__ float g_deg[NT];
__device__ float g_csum[192];
__device__ float g_updB[256 * 64];
__device__ float g_scoreB[256];
__device__ int   g_ptr[NN + 1];
__device__ int   g_cur[NN];
__device__ int   g_cnt[NN];
__device__ int   g_adj[EDOUB];
__device__ int   g_wlist[NT];
__device__ int   g_dirty[NT];
__device__ int   g_dlist[512];
__device__ int   g_nd;
__device__ unsigned g_binsA[2048];   // count histogram
__device__ unsigned g_binsB[2048];   // weight histogram
__device__ float g_pna;
__device__ float g_thr;
__device__ float g_T;
__device__ unsigned g_prefixC, g_kremC, g_prefixW, g_kremW;
__device__ int g_wl;
__device__ int g_ticket;

// ------------------------- helpers -------------------------
__device__ __forceinline__ unsigned f2key(float f) {
    unsigned u = __float_as_uint(f);
    return (u & 0x80000000u) ? ~u : (u | 0x80000000u);
}
__device__ __forceinline__ float key2f(unsigned key) {
    unsigned u = (key & 0x80000000u) ? (key & 0x7FFFFFFFu) : ~key;
    return __uint_as_float(u);
}

__device__ __forceinline__ void warpHistAdd(unsigned* bins, unsigned bin, unsigned w, unsigned NB) {
    unsigned m = __match_any_sync(0xffffffffu, bin);
    int lane = threadIdx.x & 31;
    int leader = __ffs(m) - 1;
    unsigned tot = 0;
    #pragma unroll
    for (int j = 0; j < 32; j++) {
        unsigned bj = __shfl_sync(0xffffffffu, bin, j);
        unsigned wj = __shfl_sync(0xffffffffu, w, j);
        if (bj == bin) tot += wj;
    }
    if (bin < NB && lane == leader && tot > 0) atomicAdd(&bins[bin], tot);
}

// ------------------------- setup kernels -------------------------
__global__ void k_init() {
    int i = blockIdx.x * blockDim.x + threadIdx.x;
    if (i < NT) { g_score[i] = 0.0f; g_dirty[i] = 0; }
    if (i < NN) g_cnt[i] = 0;
    if (i == 0) g_nd = 0;
}

__global__ void k_count(const int* __restrict__ ei) {
    int e = blockIdx.x * blockDim.x + threadIdx.x;
    if (e >= EDOUB) return;
    int dst = ei[(e + EORIG) % EDOUB];
    atomicAdd(&g_cnt[dst], 1);
}

__global__ void k_scan() {  // 1 block, 1024 threads
    __shared__ unsigned cs[1024];
    __shared__ float ps[1024];
    int t = threadIdx.x;
    unsigned loc[10];
    unsigned s = 0; float pl = 0.0f;
    #pragma unroll
    for (int i = 0; i < 10; i++) {
        int idx = t * 10 + i;
        unsigned c = (idx < NN) ? (unsigned)g_cnt[idx] : 0u;
        loc[i] = c; s += c;
        if (idx < NN) pl += logf((float)c + 1.0f);
    }
    cs[t] = s; ps[t] = pl;
    __syncthreads();
    for (int off = 1; off < 1024; off <<= 1) {
        unsigned v = (t >= off) ? cs[t - off] : 0u;
        __syncthreads();
        cs[t] += v;
        __syncthreads();
    }
    unsigned run = cs[t] - s;
    #pragma unroll
    for (int i = 0; i < 10; i++) {
        int idx = t * 10 + i;
        if (idx < NN) { g_ptr[idx] = (int)run; g_cur[idx] = (int)run; run += loc[i]; }
    }
    if (t == 1023) g_ptr[NN] = (int)cs[1023];
    for (int off = 512; off > 0; off >>= 1) {
        __syncthreads();
        if (t < off) ps[t] += ps[t + off];
    }
    __syncthreads();
    if (t == 0) g_pna = ps[0] / (float)NN;
}

__global__ void k_scatter(const int* __restrict__ ei, const int* __restrict__ ea) {
    int e = blockIdx.x * blockDim.x + threadIdx.x;
    if (e >= EDOUB) return;
    int src = ei[e];
    int dst = ei[(e + EORIG) % EDOUB];
    int a   = ea[e % EORIG];
    int pos = atomicAdd(&g_cur[dst], 1);
    g_adj[pos] = src | (a << 16);
}

__global__ void k_inithidden(const float* __restrict__ text,
                             const int* __restrict__ h_index,
                             const float* __restrict__ hstates) {
    int idx = blockIdx.x * blockDim.x + threadIdx.x;   // float4 index
    if (idx >= NT * 16) return;
    int v = idx >> 4, q = idx & 15;
    float4 val = make_float4(0, 0, 0, 0);
    if (v < NN) val = *(const float4*)(text + (size_t)v * DD + q * 4);
    int b = v / NN;
    int h0b = h_index[b * 16] + b * NN;
    if (v == h0b) val = *(const float4*)(hstates + b * DD + q * 4);
    *(float4*)(g_hidden + (size_t)v * DD + q * 4) = val;
}

__global__ void k_repack(const float* __restrict__ convW) {
    int idx = blockIdx.x * blockDim.x + threadIdx.x;
    if (idx >= 3 * 256 * 192) return;
    int l = idx / 49152;
    int rem = idx % 49152;
    int kk = rem / 192, j = rem % 192;
    int g = j >> 6, c = j & 63;
    g_Wcat[idx] = convW[(l * 768 + g * 256 + kk) * 64 + c];
}

// colsum of std-block of layer-0 Wcat, scaled by sqrt(1e-6)
__global__ void k_csum() {  // 1 block, 192 threads; after k_repack
    int j = threadIdx.x;
    float s = 0.0f;
    for (int k = 192; k < 256; k++) s += g_Wcat[k * 192 + j];
    g_csum[j] = s * sqrtf(1e-6f);
}

__global__ void k_qpart(const int* __restrict__ r_index,
                        const float* __restrict__ relT,
                        const float* __restrict__ Wlin,
                        const float* __restrict__ blin) {
    int j = threadIdx.x;
    if (j >= DD) return;
    int r0 = r_index[0];
    float acc = blin[j];
    for (int d = 0; d < DD; d++)
        acc += relT[r0 * DD + d] * Wlin[(DD + d) * DD + j];
    g_qpart[j] = acc;
}

__global__ void k_headscore(const int* __restrict__ h_index,
                            const int* __restrict__ r_index,
                            const float* __restrict__ hstates,
                            const float* __restrict__ relT,
                            const float* __restrict__ Wlin,
                            const float* __restrict__ blin,
                            const float* __restrict__ W1,
                            const float* __restrict__ b1,
                            const float* __restrict__ W2,
                            const float* __restrict__ b2) {
    __shared__ float sx[4][64];
    int t = threadIdx.x;      // 128 threads = 4 warps
    int b = t >> 5, ln = t & 31;
    int r0 = r_index[b * 16];
    int h0b = h_index[b * 16] + b * NN;
    const float* hv = hstates + b * DD;
    const float* rv = relT + r0 * DD;
    #pragma unroll
    for (int half = 0; half < 2; half++) {
        int c = ln + half * 32;
        float acc = blin[c];
        for (int d = 0; d < DD; d++)
            acc += hv[d] * Wlin[d * DD + c] + rv[d] * Wlin[(DD + d) * DD + c];
        sx[b][c] = hv[c] * acc;
    }
    __syncwarp();
    float sp = 0.0f;
    #pragma unroll
    for (int oo = 0; oo < 4; oo++) {
        int o = ln * 4 + oo;
        float a2 = b1[o];
        for (int d = 0; d < DD; d++) a2 += sx[b][d] * W1[d * 128 + o];
        a2 = fmaxf(a2, 0.0f);
        sp += a2 * W2[o];
    }
    #pragma unroll
    for (int off = 16; off > 0; off >>= 1)
        sp += __shfl_down_sync(0xffffffffu, sp, off);
    if (ln == 0) g_score[h0b] = sp + b2[0];
}

// Build per-copy dirty sets D_b = {h_b} ∪ outN(h_b); sets g_wl = NN + nd.
__global__ void k_dirty(const int* __restrict__ h_index) {  // 1 block, 128 threads
    int wb = threadIdx.x >> 5, ln = threadIdx.x & 31;
    int h = h_index[wb * 16];
    int p0 = g_ptr[h], p1 = g_ptr[h + 1];
    if (ln == 0) {
        int v = wb * NN + h;
        if (atomicExch(&g_dirty[v], 1) == 0) { int pos = atomicAdd(&g_nd, 1); g_dlist[pos] = v; }
    }
    for (int p = p0 + ln; p < p1; p += 32) {
        int u = g_adj[p] & 0xFFFF;
        int v = wb * NN + u;
        if (atomicExch(&g_dirty[v], 1) == 0) { int pos = atomicAdd(&g_nd, 1); g_dlist[pos] = v; }
    }
    __syncthreads();
    if (threadIdx.x == 0) g_wl = NN + g_nd;
}

// Layer-0 copies 1-3 base: everything is a function of degree only.
// updB(deg) = relu(csum0 + amp*csum1 + att*csum2 + convb); scoreB(deg) = MLP.
__global__ void k_baseB(const float* __restrict__ Wlin,
                        const float* __restrict__ W1,
                        const float* __restrict__ b1,
                        const float* __restrict__ W2,
                        const float* __restrict__ b2,
                        const float* __restrict__ convb) {  // grid 256, block 64
    __shared__ float supd[64], sx[64], sred[64];
    int deg = blockIdx.x;
    int t = threadIdx.x;
    float pna = g_pna;
    float sl = logf((float)deg + 1.0f);
    float amp = sl / pna;
    float att = pna / (sl + 1e-6f);
    float u = g_csum[t] + amp * g_csum[64 + t] + att * g_csum[128 + t] + convb[t];
    u = fmaxf(u, 0.0f);
    supd[t] = u;
    __syncthreads();
    float heur = g_qpart[t];
    for (int d = 0; d < 64; d++) heur += supd[d] * Wlin[d * DD + t];
    sx[t] = supd[t] * heur;
    __syncthreads();
    float p = 0.0f;
    #pragma unroll
    for (int oo = 0; oo < 2; oo++) {
        int o = t * 2 + oo;
        float a = b1[o];
        for (int d = 0; d < 64; d++) a += sx[d] * W1[d * 128 + o];
        p += fmaxf(a, 0.0f) * W2[o];
    }
    sred[t] = p;
    __syncthreads();
    for (int off = 32; off > 0; off >>= 1) {
        if (t < off) sred[t] += sred[t + off];
        __syncthreads();
    }
    g_updB[deg * 64 + t] = u;
    if (t == 0) g_scoreB[deg] = sred[0] + b2[0];
}

// Broadcast degree-keyed layer-0 results to copies 1-3 (non-dirty, deg>0).
__global__ void k_bcastB() {
    int idx = blockIdx.x * blockDim.x + threadIdx.x;   // [0, 3*NN*16)
    if (idx >= 3 * NN * 16) return;
    int v = NN + (idx >> 4), q = idx & 15;
    if (g_dirty[v]) return;
    int lv = v - (v / NN) * NN;
    int deg = g_ptr[lv + 1] - g_ptr[lv];
    if (deg <= 0) return;             // hidden stays 0, score stays 0
    int dc = min(deg, 255);
    float4 uv = *(const float4*)(g_updB + dc * 64 + q * 4);
    *(float4*)(g_hidden + (size_t)v * DD + q * 4) = uv;
    if (q == 0) g_score[v] = g_scoreB[dc];
}

// ------------------------- dual-threshold 3-pass radix select -------------
__global__ void k_sel2(int pass) {  // grid 157, block 256
    const int shift = (pass == 0) ? 21 : (pass == 1) ? 10 : 0;
    const unsigned nb = (pass == 2) ? 1024u : 2048u;
    int i = blockIdx.x * blockDim.x + threadIdx.x;
    unsigned prefC = 0, prefW = 0;
    if (pass > 0) { prefC = g_prefixC; prefW = g_prefixW; }
    unsigned binC = 0xFFFFFFFFu, binW = 0xFFFFFFFFu, w = 0;
    if (i < NT) {
        unsigned key = f2key(g_score[i]);
        int lv = i - (i / NN) * NN;
        w = (unsigned)(g_ptr[lv + 1] - g_ptr[lv]);
        bool mC, mW;
        if (pass == 0) { mC = true; mW = true; }
        else if (pass == 1) { mC = ((key >> 21) == (prefC >> 21)); mW = ((key >> 21) == (prefW >> 21)); }
        else { mC = ((key >> 10) == (prefC >> 10)); mW = ((key >> 10) == (prefW >> 10)); }
        unsigned bb = (key >> shift) & (nb - 1u);
        if (mC) binC = bb;
        if (mW) binW = bb;
    }
    warpHistAdd(g_binsA, binC, 1, nb);
    warpHistAdd(g_binsB, binW, w, nb);
    __threadfence();
    __shared__ int lastf;
    if (threadIdx.x == 0) lastf = (atomicAdd(&g_ticket, 1) == (int)gridDim.x - 1);
    __syncthreads();
    if (!lastf) return;
    int t = threadIdx.x;
    __shared__ unsigned ss[256];
    __shared__ unsigned rBin, rKrem;
    __shared__ float sThr, sTw;
    const int chunk = (int)(nb >> 8);
    // count pick
    {
        unsigned loc[8]; unsigned s = 0;
        #pragma unroll
        for (int j = 0; j < 8; j++) { loc[j] = (j < chunk) ? g_binsA[t * chunk + j] : 0u; s += loc[j]; }
        ss[t] = s;
        __syncthreads();
        for (int off = 1; off < 256; off <<= 1) {
            unsigned v = (t + off < 256) ? ss[t + off] : 0u;
            __syncthreads();
            ss[t] += v;
            __syncthreads();
        }
        unsigned kk = (pass == 0) ? KS_N : g_kremC;
        unsigned cumTop = (t < 255) ? ss[t + 1] : 0u;
        if (cumTop < kk && cumTop + s >= kk) {
            unsigned c = cumTop;
            for (int j = chunk - 1; j >= 0; j--) {
                if (c + loc[j] >= kk) { rBin = (unsigned)(t * chunk + j); rKrem = kk - c; break; }
                c += loc[j];
            }
        }
        __syncthreads();
        if (t == 0) {
            unsigned npref = prefC | (rBin << shift);
            if (pass < 2) { g_prefixC = npref; g_kremC = rKrem; }
            else sThr = key2f(npref);
        }
        __syncthreads();
    }
    // weight pick (over all nodes; T = max(thr, Tw) below)
    {
        unsigned loc[8]; unsigned s = 0;
        #pragma unroll
        for (int j = 0; j < 8; j++) { loc[j] = (j < chunk) ? g_binsB[t * chunk + j] : 0u; s += loc[j]; }
        ss[t] = s;
        __syncthreads();
        for (int off = 1; off < 256; off <<= 1) {
            unsigned v = (t + off < 256) ? ss[t + off] : 0u;
            __syncthreads();
            ss[t] += v;
            __syncthreads();
        }
        unsigned kk = (pass == 0) ? ES_E : g_kremW;
        unsigned cumTop = (t < 255) ? ss[t + 1] : 0u;
        if (cumTop < kk && cumTop + s >= kk) {
            unsigned c = cumTop;
            for (int j = chunk - 1; j >= 0; j--) {
                if (c + loc[j] >= kk) { rBin = (unsigned)(t * chunk + j); rKrem = kk - c; break; }
                c += loc[j];
            }
        }
        __syncthreads();
        if (t == 0) {
            unsigned npref = prefW | (rBin << shift);
            if (pass < 2) { g_prefixW = npref; g_kremW = rKrem; }
            else sTw = key2f(npref);
        }
        __syncthreads();
    }
    #pragma unroll
    for (int j = 0; j < 8; j++)
        if (j < chunk) { g_binsA[t * chunk + j] = 0; g_binsB[t * chunk + j] = 0; }
    if (t == 0) {
        g_ticket = 0;
        if (pass == 2) { g_thr = sThr; g_T = fmaxf(sThr, sTw); g_wl = 0; }
    }
}

// ------------------------- aggregation kernels -------------------------
__device__ __forceinline__ void writeFeat(int row, int lane, int deg,
                                          float s0, float s1, float q0, float q1,
                                          float mx0, float mx1, float mn0, float mn1) {
    int d0 = lane, d1 = lane + 32;
    float fdeg = (float)deg;
    float den = fmaxf(fdeg, 1.0f);
    float me0 = s0 / den, me1 = s1 / den;
    float sd0 = sqrtf(fmaxf(q0 / den - me0 * me0, 0.0f) + 1e-6f);
    float sd1 = sqrtf(fmaxf(q1 / den - me1 * me1, 0.0f) + 1e-6f);
    if (deg == 0) { mx0 = 0; mx1 = 0; mn0 = 0; mn1 = 0; }
    float* F = g_feat + (size_t)row * 256;
    F[d0] = me0;        F[d1] = me1;
    F[64 + d0] = mx0;   F[64 + d1] = mx1;
    F[128 + d0] = mn0;  F[128 + d1] = mn1;
    F[192 + d0] = sd0;  F[192 + d1] = sd1;
    if (lane == 0) g_deg[row] = fdeg;
}

// Layer-0 copy-0 base: gates 0.5, hidden = text, all edges pass.
__global__ void k_aggBase(const float* __restrict__ text, const float* __restrict__ relw) {
    int v = blockIdx.x * 8 + (threadIdx.x >> 5);   // grid 1250
    if (v >= NN) return;
    int lane = threadIdx.x & 31;
    int d0 = lane, d1 = lane + 32;
    const float* rw = relw;   // l = 0
    int p0 = g_ptr[v], p1 = g_ptr[v + 1];
    float s0 = 0, s1 = 0, q0 = 0, q1 = 0;
    float mx0 = -INFINITY, mx1 = -INFINITY, mn0 = INFINITY, mn1 = INFINITY;
    int deg = 0;
    for (int p = p0; p < p1; p++) {
        int pk = __ldg(&g_adj[p]);
        int u = pk & 0xFFFF, a = pk >> 16;
        float m0 = 0.5f * text[(size_t)u * DD + d0] * rw[a * DD + d0];
        float m1 = 0.5f * text[(size_t)u * DD + d1] * rw[a * DD + d1];
        s0 += m0; q0 += m0 * m0; mx0 = fmaxf(mx0, m0); mn0 = fminf(mn0, m0);
        s1 += m1; q1 += m1 * m1; mx1 = fmaxf(mx1, m1); mn1 = fminf(mn1, m1);
        deg++;
    }
    writeFeat(v, lane, deg, s0, s1, q0, q1, mx0, mx1, mn0, mn1);
}

// Layer-0 dirty: exact per-copy agg with T=0. Row = NN + j.
__global__ void k_aggDirty(const float* __restrict__ relw) {
    int j = blockIdx.x * 8 + (threadIdx.x >> 5);   // grid 64
    if (j >= g_nd) return;
    int lane = threadIdx.x & 31;
    int v = g_dlist[j];
    int base = (v / NN) * NN;
    int lv = v - base;
    int d0 = lane, d1 = lane + 32;
    const float* rw = relw;   // l = 0
    int p0 = g_ptr[lv], p1 = g_ptr[lv + 1];
    float s0 = 0, s1 = 0, q0 = 0, q1 = 0;
    float mx0 = -INFINITY, mx1 = -INFINITY, mn0 = INFINITY, mn1 = INFINITY;
    int deg = 0;
    for (int p = p0; p < p1; p++) {
        int pk = __ldg(&g_adj[p]);
        int u = pk & 0xFFFF, a = pk >> 16;
        int gu = base + u;
        float sc = g_score[gu];
        if (sc >= 0.0f) {
            float wgt = 1.0f / (1.0f + __expf(-sc));
            float m0 = wgt * g_hidden[(size_t)gu * DD + d0] * rw[a * DD + d0];
            float m1 = wgt * g_hidden[(size_t)gu * DD + d1] * rw[a * DD + d1];
            s0 += m0; q0 += m0 * m0; mx0 = fmaxf(mx0, m0); mn0 = fminf(mn0, m0);
            s1 += m1; q1 += m1 * m1; mx1 = fmaxf(mx1, m1); mn1 = fminf(mn1, m1);
            deg++;
        }
    }
    writeFeat(NN + j, lane, deg, s0, s1, q0, q1, mx0, mx1, mn0, mn1);
}

// Layers 1-2: fused worklist + exact agg.
__global__ void k_aggSel(const float* __restrict__ relw, int l) {
    int i = blockIdx.x * 8 + (threadIdx.x >> 5);   // grid 5000
    if (i >= NT) return;
    int lane = threadIdx.x & 31;
    int base = (i / NN) * NN;
    int lv = i - base;
    int p0 = g_ptr[lv], p1 = g_ptr[lv + 1];
    float T = g_T;
    if (p1 == p0 || !(g_score[i] >= T)) return;
    int row = 0;
    if (lane == 0) row = atomicAdd(&g_wl, 1);
    row = __shfl_sync(0xffffffffu, row, 0);
    int d0 = lane, d1 = lane + 32;
    const float* rw = relw + l * 400 * DD;
    float s0 = 0, s1 = 0, q0 = 0, q1 = 0;
    float mx0 = -INFINITY, mx1 = -INFINITY, mn0 = INFINITY, mn1 = INFINITY;
    int deg = 0;
    for (int p = p0; p < p1; p++) {
        int pk = __ldg(&g_adj[p]);
        int u = pk & 0xFFFF, a = pk >> 16;
        int gu = base + u;
        float sc = g_score[gu];
        if (sc >= T) {
            float wgt = 1.0f / (1.0f + __expf(-sc));
            float m0 = wgt * g_hidden[(size_t)gu * DD + d0] * rw[a * DD + d0];
            float m1 = wgt * g_hidden[(size_t)gu * DD + d1] * rw[a * DD + d1];
            s0 += m0; q0 += m0 * m0; mx0 = fmaxf(mx0, m0); mn0 = fminf(mn0, m0);
            s1 += m1; q1 += m1 * m1; mx1 = fmaxf(mx1, m1); mn1 = fminf(mn1, m1);
            deg++;
        }
    }
    writeFeat(row, lane, deg, s0, s1, q0, q1, mx0, mx1, mn0, mn1);
    if (lane == 0) g_wlist[row] = i;
}

// C[cnt,192] = feat[cnt,256] @ Wcat[256,192]; 128x64 tile, 8x4 micro-tile
__global__ void k_gemm(int l) {
    __shared__ float sA[16 * 128];
    __shared__ float sB[16 * 64];
    int cnt = g_wl;
    int rowBase = blockIdx.x * 128;
    if (rowBase >= cnt) return;
    int colBase = blockIdx.y * 64;
    int t = threadIdx.x;
    int tx = t & 15, ty = t >> 4;
    const float* Wb = g_Wcat + l * 256 * 192;
    float acc[8][4] = {};
    for (int k0 = 0; k0 < 256; k0 += 16) {
        #pragma unroll
        for (int q = 0; q < 2; q++) {
            int lin = t * 2 + q;
            int r = lin >> 2, kq = lin & 3;
            float4 av = make_float4(0, 0, 0, 0);
            int row = rowBase + r;
            if (row < cnt) av = *(const float4*)(g_feat + (size_t)row * 256 + k0 + kq * 4);
            sA[(kq * 4 + 0) * 128 + r] = av.x;
            sA[(kq * 4 + 1) * 128 + r] = av.y;
            sA[(kq * 4 + 2) * 128 + r] = av.z;
            sA[(kq * 4 + 3) * 128 + r] = av.w;
        }
        {
            int kb = t >> 4, j4 = (t & 15) * 4;
            float4 bv = *(const float4*)(Wb + (size_t)(k0 + kb) * 192 + colBase + j4);
            *(float4*)&sB[kb * 64 + j4] = bv;
        }
        __syncthreads();
        #pragma unroll
        for (int kk = 0; kk < 16; kk++) {
            float4 a0 = *(float4*)&sA[kk * 128 + ty * 8];
            float4 a1 = *(float4*)&sA[kk * 128 + ty * 8 + 4];
            float4 b0 = *(float4*)&sB[kk * 64 + tx * 4];
            float a[8] = {a0.x, a0.y, a0.z, a0.w, a1.x, a1.y, a1.z, a1.w};
            float bb[4] = {b0.x, b0.y, b0.z, b0.w};
            #pragma unroll
            for (int i = 0; i < 8; i++)
                #pragma unroll
                for (int j = 0; j < 4; j++)
                    acc[i][j] += a[i] * bb[j];
        }
        __syncthreads();
    }
    #pragma unroll
    for (int i = 0; i < 8; i++) {
        int row = rowBase + ty * 8 + i;
        if (row < cnt) {
            float4 v = make_float4(acc[i][0], acc[i][1], acc[i][2], acc[i][3]);
            *(float4*)(g_C + (size_t)row * 192 + colBase + tx * 4) = v;
        }
    }
}

// Generic fused post (layers 1-2): hidden update + heuristic GEMM + score MLP.
__global__ void k_post(const float* __restrict__ convb,
                       const float* __restrict__ Wlin,
                       const float* __restrict__ W1,
                       const float* __restrict__ b1,
                       const float* __restrict__ W2,
                       const float* __restrict__ b2, int l) {
    extern __shared__ float smem[];
    float* sh   = smem;
    float* sbuf = smem + 64 * 65;
    float* sqp  = sbuf + 64 * 128;
    float* samp = sqp + 64;
    float* satt = samp + 64;
    float* sw2  = satt + 64;
    float* sb1  = sw2 + 128;
    int*   sv   = (int*)(sb1 + 128);

    int cnt = g_wl;
    int rowBase = blockIdx.x * 64;
    if (rowBase >= cnt) return;
    int t = threadIdx.x;

    if (t < 64) {
        int i = rowBase + t;
        float dg = (i < cnt) ? g_deg[i] : 0.0f;
        float sl = logf(dg + 1.0f);
        float pna = g_pna;
        samp[t] = sl / pna;
        satt[t] = pna / (sl + 1e-6f);
        sv[t] = (i < cnt) ? g_wlist[i] : -1;
        sqp[t] = g_qpart[t];
    }
    if (t < 128) { sw2[t] = W2[t]; sb1[t] = b1[t]; }
    __syncthreads();

    #pragma unroll
    for (int q = 0; q < 16; q++) {
        int lin = t + q * 256;
        int r = lin >> 6, d = lin & 63;
        int i = rowBase + r;
        float nh = 0.0f;
        if (i < cnt) {
            const float* C = g_C + (size_t)i * 192;
            float u = C[d] + samp[r] * C[64 + d] + satt[r] * C[128 + d] + convb[l * 64 + d];
            u = fmaxf(u, 0.0f);
            int v = sv[r];
            nh = g_hidden[(size_t)v * DD + d] + u;
            g_hidden[(size_t)v * DD + d] = nh;
        }
        sh[r * 65 + d] = nh;
    }
    #pragma unroll
    for (int q = 0; q < 16; q++) {
        int lin = t + q * 256;
        int r = lin >> 6, c = lin & 63;
        sbuf[r * 68 + c] = Wlin[r * DD + c];
    }
    __syncthreads();

    int tx = t & 15, ty = t >> 4;
    {
        float acc[4][4] = {};
        for (int k = 0; k < 64; k++) {
            float a[4], bb[4];
            #pragma unroll
            for (int i = 0; i < 4; i++) a[i] = sh[(ty * 4 + i) * 65 + k];
            float4 b4 = *(float4*)&sbuf[k * 68 + tx * 4];
            bb[0] = b4.x; bb[1] = b4.y; bb[2] = b4.z; bb[3] = b4.w;
            #pragma unroll
            for (int i = 0; i < 4; i++)
                #pragma unroll
                for (int j = 0; j < 4; j++)
                    acc[i][j] += a[i] * bb[j];
        }
        __syncthreads();
        #pragma unroll
        for (int i = 0; i < 4; i++)
            #pragma unroll
            for (int j = 0; j < 4; j++) {
                int r = ty * 4 + i, c = tx * 4 + j;
                float hv = sh[r * 65 + c];
                sh[r * 65 + c] = hv * (acc[i][j] + sqp[c]);
            }
        __syncthreads();
    }

    #pragma unroll
    for (int q = 0; q < 32; q++) {
        int lin = t + q * 256;
        sbuf[lin] = W1[lin];
    }
    __syncthreads();

    {
        float acc[4][8] = {};
        for (int k = 0; k < 64; k++) {
            float a[4];
            #pragma unroll
            for (int i = 0; i < 4; i++) a[i] = sh[(ty * 4 + i) * 65 + k];
            float4 b0 = *(float4*)&sbuf[k * 128 + tx * 8];
            float4 b1v = *(float4*)&sbuf[k * 128 + tx * 8 + 4];
            float bb[8] = {b0.x, b0.y, b0.z, b0.w, b1v.x, b1v.y, b1v.z, b1v.w};
            #pragma unroll
            for (int i = 0; i < 4; i++)
                #pragma unroll
                for (int j = 0; j < 8; j++)
                    acc[i][j] += a[i] * bb[j];
        }
        float bias2 = b2[0];
        #pragma unroll
        for (int i = 0; i < 4; i++) {
            float p = 0.0f;
            #pragma unroll
            for (int j = 0; j < 8; j++) {
                int o = tx * 8 + j;
                p += fmaxf(acc[i][j] + sb1[o], 0.0f) * sw2[o];
            }
            p += __shfl_xor_sync(0xffffffffu, p, 1);
            p += __shfl_xor_sync(0xffffffffu, p, 2);
            p += __shfl_xor_sync(0xffffffffu, p, 4);
            p += __shfl_xor_sync(0xffffffffu, p, 8);
            if ((t & 15) == 0) {
                int i2 = rowBase + ty * 4 + i;
                if (i2 < cnt) {
                    int v = sv[ty * 4 + i];
                    g_score[v] = p + bias2;
                }
            }
        }
    }
}

// Layer-0 post: rows 0..NN-1 = copy-0 base (skip copy-0 dirty), rows NN.. = dirty.
__global__ void k_post0(const float* __restrict__ text,
                        const float* __restrict__ convb,
                        const float* __restrict__ Wlin,
                        const float* __restrict__ W1,
                        const float* __restrict__ b1,
                        const float* __restrict__ W2,
                        const float* __restrict__ b2) {
    extern __shared__ float smem[];
    float* sh   = smem;
    float* sbuf = smem + 64 * 65;
    float* sqp  = sbuf + 64 * 128;
    float* samp = sqp + 64;
    float* satt = samp + 64;
    float* sw2  = satt + 64;
    float* sb1  = sw2 + 128;
    int*   svg  = (int*)(sb1 + 128);
    int*   som  = svg + 64;   // bit0 omask, bit1 isbase(copy0), bit2 copy0-dirty

    int cnt = g_wl;
    int rowBase = blockIdx.x * 64;
    if (rowBase >= cnt) return;
    int t = threadIdx.x;

    if (t < 64) {
        int i = rowBase + t;
        float dg = 0.0f; int vg = 0; int flags = 0;
        if (i < cnt) {
            dg = g_deg[i];
            if (i < NN) {
                vg = i;
                flags = 2 | ((g_ptr[i + 1] > g_ptr[i]) ? 1 : 0) | (g_dirty[i] ? 4 : 0);
            } else {
                int v = g_dlist[i - NN]; vg = v;
                int lv = v - (v / NN) * NN;
                int sdeg = g_ptr[lv + 1] - g_ptr[lv];
                flags = ((g_score[v] >= 0.0f) && sdeg > 0) ? 1 : 0;
            }
        }
        float sl = logf(dg + 1.0f);
        float pna = g_pna;
        samp[t] = sl / pna;
        satt[t] = pna / (sl + 1e-6f);
        svg[t] = vg; som[t] = flags;
        sqp[t] = g_qpart[t];
    }
    if (t < 128) { sw2[t] = W2[t]; sb1[t] = b1[t]; }
    __syncthreads();

    #pragma unroll
    for (int q = 0; q < 16; q++) {
        int lin = t + q * 256;
        int r = lin >> 6, d = lin & 63;
        int i = rowBase + r;
        float nh = 0.0f;
        if (i < cnt) {
            int flags = som[r]; int vg = svg[r];
            float pre = (flags & 2) ? text[(size_t)vg * DD + d]
                                    : g_hidden[(size_t)vg * DD + d];
            float u = 0.0f;
            if (flags & 1) {
                const float* C = g_C + (size_t)i * 192;
                u = fmaxf(C[d] + samp[r] * C[64 + d] + satt[r] * C[128 + d] + convb[d], 0.0f);
            }
            nh = pre + u;
            if (flags & 2) {
                if (!(flags & 4)) g_hidden[(size_t)vg * DD + d] = nh;  // copy 0 only
            } else {
                g_hidden[(size_t)vg * DD + d] = nh;
            }
        }
        sh[r * 65 + d] = nh;
    }
    #pragma unroll
    for (int q = 0; q < 16; q++) {
        int lin = t + q * 256;
        int r = lin >> 6, c = lin & 63;
        sbuf[r * 68 + c] = Wlin[r * DD + c];
    }
    __syncthreads();

    int tx = t & 15, ty = t >> 4;
    {
        float acc[4][4] = {};
        for (int k = 0; k < 64; k++) {
            float a[4], bb[4];
            #pragma unroll
            for (int i = 0; i < 4; i++) a[i] = sh[(ty * 4 + i) * 65 + k];
            float4 b4 = *(float4*)&sbuf[k * 68 + tx * 4];
            bb[0] = b4.x; bb[1] = b4.y; bb[2] = b4.z; bb[3] = b4.w;
            #pragma unroll
            for (int i = 0; i < 4; i++)
                #pragma unroll
                for (int j = 0; j < 4; j++)
                    acc[i][j] += a[i] * bb[j];
        }
        __syncthreads();
        #pragma unroll
        for (int i = 0; i < 4; i++)
            #pragma unroll
            for (int j = 0; j < 4; j++) {
                int r = ty * 4 + i, c = tx * 4 + j;
                float hv = sh[r * 65 + c];
                sh[r * 65 + c] = hv * (acc[i][j] + sqp[c]);
            }
        __syncthreads();
    }

    #pragma unroll
    for (int q = 0; q < 32; q++) {
        int lin = t + q * 256;
        sbuf[lin] = W1[lin];
    }
    __syncthreads();

    {
        float acc[4][8] = {};
        for (int k = 0; k < 64; k++) {
            float a[4];
            #pragma unroll
            for (int i = 0; i < 4; i++) a[i] = sh[(ty * 4 + i) * 65 + k];
            float4 b0 = *(float4*)&sbuf[k * 128 + tx * 8];
            float4 b1v = *(float4*)&sbuf[k * 128 + tx * 8 + 4];
            float bb[8] = {b0.x, b0.y, b0.z, b0.w, b1v.x, b1v.y, b1v.z, b1v.w};
            #pragma unroll
            for (int i = 0; i < 4; i++)
                #pragma unroll
                for (int j = 0; j < 8; j++)
                    acc[i][j] += a[i] * bb[j];
        }
        float bias2 = b2[0];
        #pragma unroll
        for (int i = 0; i < 4; i++) {
            float p = 0.0f;
            #pragma unroll
            for (int j = 0; j < 8; j++) {
                int o = tx * 8 + j;
                p += fmaxf(acc[i][j] + sb1[o], 0.0f) * sw2[o];
            }
            p += __shfl_xor_sync(0xffffffffu, p, 1);
            p += __shfl_xor_sync(0xffffffffu, p, 2);
            p += __shfl_xor_sync(0xffffffffu, p, 4);
            p += __shfl_xor_sync(0xffffffffu, p, 8);
            if ((t & 15) == 0) {
                int i2 = rowBase + ty * 4 + i;
                if (i2 < cnt) {
                    int flags = som[ty * 4 + i];
                    int vg = svg[ty * 4 + i];
                    float sc = p + bias2;
                    if (flags & 2) {
                        if ((flags & 1) && !(flags & 4)) g_score[vg] = sc;
                    } else if (flags & 1) {
                        g_score[vg] = sc;
                    }
                }
            }
        }
    }
}

__global__ void k_out(const int* __restrict__ t_index, float* __restrict__ out) {
    int t = threadIdx.x;
    if (t >= 64) return;
    int b = t / 16;
    int v = t_index[t] + b * NN;
    out[t] = g_score[v];
}

// ------------------------- launch -------------------------
extern "C" void kernel_launch(void* const* d_in, const int* in_sizes, int n_in,
                              void* d_out, int out_size) {
    const int*   h_index   = (const int*)d_in[0];
    const int*   r_index   = (const int*)d_in[1];
    const int*   t_index   = (const int*)d_in[2];
    const float* hstates   = (const float*)d_in[3];
    const int*   edge_idx  = (const int*)d_in[5];
    const int*   edge_attr = (const int*)d_in[6];
    const float* text      = (const float*)d_in[7];
    const float* relT      = (const float*)d_in[9];
    const float* Wlin      = (const float*)d_in[10];
    const float* blin      = (const float*)d_in[11];
    const float* W1        = (const float*)d_in[12];
    const float* b1        = (const float*)d_in[13];
    const float* W2        = (const float*)d_in[14];
    const float* b2        = (const float*)d_in[15];
    const float* relw      = (const float*)d_in[16];
    const float* convW     = (const float*)d_in[17];
    const float* convb     = (const float*)d_in[18];
    float* out = (float*)d_out;

    const int SMEM_POST  = (64 * 65 + 64 * 128 + 64 * 3 + 128 * 2 + 64) * 4;
    const int SMEM_POST0 = (64 * 65 + 64 * 128 + 64 * 3 + 128 * 2 + 128) * 4;
    static int attr_done = 0;
    if (!attr_done) {
        cudaFuncSetAttribute(k_post, cudaFuncAttributeMaxDynamicSharedMemorySize, SMEM_POST);
        cudaFuncSetAttribute(k_post0, cudaFuncAttributeMaxDynamicSharedMemorySize, SMEM_POST0);
        attr_done = 1;
    }

    k_init<<<157, 256>>>();
    k_count<<<391, 256>>>(edge_idx);
    k_scan<<<1, 1024>>>();
    k_scatter<<<391, 256>>>(edge_idx, edge_attr);
    k_inithidden<<<2500, 256>>>(text, h_index, hstates);
    k_repack<<<576, 256>>>(convW);
    k_csum<<<1, 192>>>();
    k_qpart<<<1, 64>>>(r_index, relT, Wlin, blin);
    k_headscore<<<1, 128>>>(h_index, r_index, hstates, relT, Wlin, blin, W1, b1, W2, b2);
    k_dirty<<<1, 128>>>(h_index);

    // ---- layer 0 (thr = T = 0 statically) ----
    k_baseB<<<256, 64>>>(Wlin, W1, b1, W2, b2, convb);   // copies 1-3 by degree
    k_aggBase<<<1250, 256>>>(text, relw);                 // copy-0 base agg
    k_aggDirty<<<64, 256>>>(relw);                        // exact dirty agg
    k_gemm<<<dim3(83, 3), 256>>>(0);
    k_post0<<<165, 256, SMEM_POST0>>>(text, convb, Wlin, W1, b1, W2, b2);
    k_bcastB<<<1875, 256>>>();                            // broadcast to copies 1-3

    // ---- layers 1-2 ----
    for (int l = 1; l < 3; l++) {
        k_sel2<<<157, 256>>>(0);
        k_sel2<<<157, 256>>>(1);
        k_sel2<<<157, 256>>>(2);   // tail sets g_thr, g_T, resets g_wl
        k_aggSel<<<5000, 256>>>(relw, l);
        k_gemm<<<dim3(64, 3), 256>>>(l);
        k_post<<<128, 256, SMEM_POST>>>(convb, Wlin, W1, b1, W2, b2, l);
    }
    k_out<<<1, 64>>>(t_index, out);
}

// round 7
// speedup vs baseline: 4.4521x; 1.0844x over previous
#include <cuda_runtime.h>
#include <math.h>

#define NN 10000
#define EORIG 50000
#define EDOUB 100000
#define BB 4
#define NT 40000
#define DD 64
#define KS_N 4000u
#define ES_E 40000u

// ------------------------- device scratch (zero-initialized at load) ------
__device__ float g_hidden[NT * DD];
__device__ float g_score[NT];
__device__ float g_feat[NT * 256];
__device__ float g_C[NT * 192];
__device__ float g_Wcat[3 * 256 * 192];
__device__ float g_qpart[DD];
__device__ float g_deg[NT];
__device__ float g_csum[192];
__device__ float g_updB[256 * 64];
__device__ float g_scoreB[256];
__device__ float g_partial[40];
__device__ int   g_ptr[NN + 1];
__device__ int   g_cur[NN];
__device__ int   g_cnt[NN];
__device__ int   g_adj[EDOUB];
__device__ int   g_wlist[NT];
__device__ int   g_dirty[NT];
__device__ int   g_dlist[512];
__device__ int   g_nd;
__device__ unsigned g_binsA[2048];   // count histogram
__device__ unsigned g_binsB[2048];   // weight histogram
__device__ float g_pna;
__device__ float g_thr;
__device__ float g_T;
__device__ unsigned g_prefixC, g_kremC, g_prefixW, g_kremW;
__device__ int g_wl;
__device__ int g_ticket;

// ------------------------- helpers -------------------------
__device__ __forceinline__ unsigned f2key(float f) {
    unsigned u = __float_as_uint(f);
    return (u & 0x80000000u) ? ~u : (u | 0x80000000u);
}
__device__ __forceinline__ float key2f(unsigned key) {
    unsigned u = (key & 0x80000000u) ? (key & 0x7FFFFFFFu) : ~key;
    return __uint_as_float(u);
}

__device__ __forceinline__ void warpHistAdd(unsigned* bins, unsigned bin, unsigned w, unsigned NB) {
    unsigned m = __match_any_sync(0xffffffffu, bin);
    int lane = threadIdx.x & 31;
    int leader = __ffs(m) - 1;
    unsigned tot = 0;
    #pragma unroll
    for (int j = 0; j < 32; j++) {
        unsigned bj = __shfl_sync(0xffffffffu, bin, j);
        unsigned wj = __shfl_sync(0xffffffffu, w, j);
        if (bj == bin) tot += wj;
    }
    if (bin < NB && lane == leader && tot > 0) atomicAdd(&bins[bin], tot);
}

// ------------------------- fused setup -------------------------
// blocks [0,157): init; [157,2657): inithidden; [2657,3233): repack; 3233: csum
__global__ void k_setup(const float* __restrict__ text,
                        const int* __restrict__ h_index,
                        const float* __restrict__ hstates,
                        const float* __restrict__ convW) {
    int blk = blockIdx.x, t = threadIdx.x;
    if (blk < 157) {
        int i = blk * 256 + t;
        if (i < NT) { g_score[i] = 0.0f; g_dirty[i] = 0; }
        if (i < NN) g_cnt[i] = 0;
        if (i == 0) g_nd = 0;
    } else if (blk < 2657) {
        int idx = (blk - 157) * 256 + t;    // exactly NT*16
        int v = idx >> 4, q = idx & 15;
        float4 val = make_float4(0, 0, 0, 0);
        if (v < NN) val = *(const float4*)(text + (size_t)v * DD + q * 4);
        int b = v / NN;
        int h0b = h_index[b * 16] + b * NN;
        if (v == h0b) val = *(const float4*)(hstates + b * DD + q * 4);
        *(float4*)(g_hidden + (size_t)v * DD + q * 4) = val;
    } else if (blk < 3233) {
        int idx = (blk - 2657) * 256 + t;   // exactly 3*256*192
        int l = idx / 49152;
        int rem = idx % 49152;
        int kk = rem / 192, j = rem % 192;
        int g = j >> 6, c = j & 63;
        g_Wcat[idx] = convW[(l * 768 + g * 256 + kk) * 64 + c];
    } else {
        if (t < 192) {
            int g = t >> 6, c = t & 63;
            float s = 0.0f;
            for (int k = 192; k < 256; k++) s += convW[(g * 256 + k) * 64 + c];
            g_csum[t] = s * sqrtf(1e-6f);
        }
    }
}

__global__ void k_count(const int* __restrict__ ei) {
    int e = blockIdx.x * blockDim.x + threadIdx.x;
    if (e >= EDOUB) return;
    int dst = ei[(e + EORIG) % EDOUB];
    atomicAdd(&g_cnt[dst], 1);
}

// grid-wide deterministic partial sums of log(cnt+1)
__global__ void k_scanA() {   // grid 40, block 256
    __shared__ float ws[8];
    int t = threadIdx.x;
    int i = blockIdx.x * 256 + t;
    float v = (i < NN) ? logf((float)g_cnt[i] + 1.0f) : 0.0f;
    #pragma unroll
    for (int off = 16; off > 0; off >>= 1)
        v += __shfl_down_sync(0xffffffffu, v, off);
    if ((t & 31) == 0) ws[t >> 5] = v;
    __syncthreads();
    if (t == 0) {
        float s = 0.0f;
        #pragma unroll
        for (int w = 0; w < 8; w++) s += ws[w];
        g_partial[blockIdx.x] = s;
    }
}

__global__ void k_scan() {  // 1 block, 1024 threads: prefix sums + pna finalize
    __shared__ unsigned cs[1024];
    int t = threadIdx.x;
    unsigned loc[10];
    unsigned s = 0;
    #pragma unroll
    for (int i = 0; i < 10; i++) {
        int idx = t * 10 + i;
        unsigned c = (idx < NN) ? (unsigned)g_cnt[idx] : 0u;
        loc[i] = c; s += c;
    }
    cs[t] = s;
    __syncthreads();
    for (int off = 1; off < 1024; off <<= 1) {
        unsigned v = (t >= off) ? cs[t - off] : 0u;
        __syncthreads();
        cs[t] += v;
        __syncthreads();
    }
    unsigned run = cs[t] - s;
    #pragma unroll
    for (int i = 0; i < 10; i++) {
        int idx = t * 10 + i;
        if (idx < NN) { g_ptr[idx] = (int)run; g_cur[idx] = (int)run; run += loc[i]; }
    }
    if (t == 1023) g_ptr[NN] = (int)cs[1023];
    if (t == 0) {
        float p = 0.0f;
        for (int w = 0; w < 40; w++) p += g_partial[w];
        g_pna = p / (float)NN;
    }
}

__global__ void k_scatter(const int* __restrict__ ei, const int* __restrict__ ea) {
    int e = blockIdx.x * blockDim.x + threadIdx.x;
    if (e >= EDOUB) return;
    int src = ei[e];
    int dst = ei[(e + EORIG) % EDOUB];
    int a   = ea[e % EORIG];
    int pos = atomicAdd(&g_cur[dst], 1);
    g_adj[pos] = src | (a << 16);
}

// ------------------------- fused prep -------------------------
// blocks [0,256): baseB(deg=blk); 256: headscore; 257: dirty; 258: qpart
__global__ void k_prep(const int* __restrict__ h_index,
                       const int* __restrict__ r_index,
                       const float* __restrict__ hstates,
                       const float* __restrict__ relT,
                       const float* __restrict__ Wlin,
                       const float* __restrict__ blin,
                       const float* __restrict__ W1,
                       const float* __restrict__ b1,
                       const float* __restrict__ W2,
                       const float* __restrict__ b2,
                       const float* __restrict__ convb) {   // 128 threads
    int blk = blockIdx.x, t = threadIdx.x;
    if (blk < 256) {
        __shared__ float sqp[64], supd[64], sx[64], sred[64];
        int deg = blk;
        int r0 = r_index[0];
        if (t < 64) {
            float acc = blin[t];
            for (int d = 0; d < DD; d++)
                acc += relT[r0 * DD + d] * Wlin[(DD + d) * DD + t];
            sqp[t] = acc;
        }
        float pna = g_pna;
        float sl = logf((float)deg + 1.0f);
        float amp = sl / pna;
        float att = pna / (sl + 1e-6f);
        if (t < 64) {
            float u = g_csum[t] + amp * g_csum[64 + t] + att * g_csum[128 + t] + convb[t];
            supd[t] = fmaxf(u, 0.0f);
        }
        __syncthreads();
        if (t < 64) {
            float heur = sqp[t];
            for (int d = 0; d < 64; d++) heur += supd[d] * Wlin[d * DD + t];
            sx[t] = supd[t] * heur;
        }
        __syncthreads();
        if (t < 64) {
            float p = 0.0f;
            #pragma unroll
            for (int oo = 0; oo < 2; oo++) {
                int o = t * 2 + oo;
                float a = b1[o];
                for (int d = 0; d < 64; d++) a += sx[d] * W1[d * 128 + o];
                p += fmaxf(a, 0.0f) * W2[o];
            }
            sred[t] = p;
        }
        __syncthreads();
        for (int off = 32; off > 0; off >>= 1) {
            if (t < off) sred[t] += sred[t + off];
            __syncthreads();
        }
        if (t < 64) g_updB[deg * 64 + t] = supd[t];
        if (t == 0) g_scoreB[deg] = sred[0] + b2[0];
    } else if (blk == 256) {
        // headscore (128 threads = 4 warps)
        __shared__ float sx2[4][64];
        int b = t >> 5, ln = t & 31;
        int r0 = r_index[b * 16];
        int h0b = h_index[b * 16] + b * NN;
        const float* hv = hstates + b * DD;
        const float* rv = relT + r0 * DD;
        #pragma unroll
        for (int half = 0; half < 2; half++) {
            int c = ln + half * 32;
            float acc = blin[c];
            for (int d = 0; d < DD; d++)
                acc += hv[d] * Wlin[d * DD + c] + rv[d] * Wlin[(DD + d) * DD + c];
            sx2[b][c] = hv[c] * acc;
        }
        __syncwarp();
        float sp = 0.0f;
        #pragma unroll
        for (int oo = 0; oo < 4; oo++) {
            int o = ln * 4 + oo;
            float a2 = b1[o];
            for (int d = 0; d < DD; d++) a2 += sx2[b][d] * W1[d * 128 + o];
            a2 = fmaxf(a2, 0.0f);
            sp += a2 * W2[o];
        }
        #pragma unroll
        for (int off = 16; off > 0; off >>= 1)
            sp += __shfl_down_sync(0xffffffffu, sp, off);
        if (ln == 0) g_score[h0b] = sp + b2[0];
    } else if (blk == 257) {
        // dirty set build
        int wb = t >> 5, ln = t & 31;
        int h = h_index[wb * 16];
        int p0 = g_ptr[h], p1 = g_ptr[h + 1];
        if (ln == 0) {
            int v = wb * NN + h;
            if (atomicExch(&g_dirty[v], 1) == 0) { int pos = atomicAdd(&g_nd, 1); g_dlist[pos] = v; }
        }
        for (int p = p0 + ln; p < p1; p += 32) {
            int u = g_adj[p] & 0xFFFF;
            int v = wb * NN + u;
            if (atomicExch(&g_dirty[v], 1) == 0) { int pos = atomicAdd(&g_nd, 1); g_dlist[pos] = v; }
        }
        __syncthreads();
        if (t == 0) g_wl = NN + g_nd;
    } else {
        if (t < DD) {
            int r0 = r_index[0];
            float acc = blin[t];
            for (int d = 0; d < DD; d++)
                acc += relT[r0 * DD + d] * Wlin[(DD + d) * DD + t];
            g_qpart[t] = acc;
        }
    }
}

// ------------------------- aggregation -------------------------
__device__ __forceinline__ void writeFeat(int row, int lane, int deg,
                                          float s0, float s1, float q0, float q1,
                                          float mx0, float mx1, float mn0, float mn1) {
    int d0 = lane, d1 = lane + 32;
    float fdeg = (float)deg;
    float den = fmaxf(fdeg, 1.0f);
    float me0 = s0 / den, me1 = s1 / den;
    float sd0 = sqrtf(fmaxf(q0 / den - me0 * me0, 0.0f) + 1e-6f);
    float sd1 = sqrtf(fmaxf(q1 / den - me1 * me1, 0.0f) + 1e-6f);
    if (deg == 0) { mx0 = 0; mx1 = 0; mn0 = 0; mn1 = 0; }
    float* F = g_feat + (size_t)row * 256;
    F[d0] = me0;        F[d1] = me1;
    F[64 + d0] = mx0;   F[64 + d1] = mx1;
    F[128 + d0] = mn0;  F[128 + d1] = mn1;
    F[192 + d0] = sd0;  F[192 + d1] = sd1;
    if (lane == 0) g_deg[row] = fdeg;
}

// blocks [0,1250): copy-0 base agg; [1250,1314): dirty agg (layer 0)
__global__ void k_agg0(const float* __restrict__ text, const float* __restrict__ relw) {
    int blk = blockIdx.x;
    int lane = threadIdx.x & 31;
    int d0 = lane, d1 = lane + 32;
    const float* rw = relw;   // l = 0
    if (blk < 1250) {
        int v = blk * 8 + (threadIdx.x >> 5);
        if (v >= NN) return;
        int p0 = g_ptr[v], p1 = g_ptr[v + 1];
        float s0 = 0, s1 = 0, q0 = 0, q1 = 0;
        float mx0 = -INFINITY, mx1 = -INFINITY, mn0 = INFINITY, mn1 = INFINITY;
        int deg = 0;
        for (int p = p0; p < p1; p++) {
            int pk = __ldg(&g_adj[p]);
            int u = pk & 0xFFFF, a = pk >> 16;
            float m0 = 0.5f * text[(size_t)u * DD + d0] * rw[a * DD + d0];
            float m1 = 0.5f * text[(size_t)u * DD + d1] * rw[a * DD + d1];
            s0 += m0; q0 += m0 * m0; mx0 = fmaxf(mx0, m0); mn0 = fminf(mn0, m0);
            s1 += m1; q1 += m1 * m1; mx1 = fmaxf(mx1, m1); mn1 = fminf(mn1, m1);
            deg++;
        }
        writeFeat(v, lane, deg, s0, s1, q0, q1, mx0, mx1, mn0, mn1);
    } else {
        int j = (blk - 1250) * 8 + (threadIdx.x >> 5);
        if (j >= g_nd) return;
        int v = g_dlist[j];
        int base = (v / NN) * NN;
        int lv = v - base;
        int p0 = g_ptr[lv], p1 = g_ptr[lv + 1];
        float s0 = 0, s1 = 0, q0 = 0, q1 = 0;
        float mx0 = -INFINITY, mx1 = -INFINITY, mn0 = INFINITY, mn1 = INFINITY;
        int deg = 0;
        for (int p = p0; p < p1; p++) {
            int pk = __ldg(&g_adj[p]);
            int u = pk & 0xFFFF, a = pk >> 16;
            int gu = base + u;
            float sc = g_score[gu];
            if (sc >= 0.0f) {
                float wgt = 1.0f / (1.0f + __expf(-sc));
                float m0 = wgt * g_hidden[(size_t)gu * DD + d0] * rw[a * DD + d0];
                float m1 = wgt * g_hidden[(size_t)gu * DD + d1] * rw[a * DD + d1];
                s0 += m0; q0 += m0 * m0; mx0 = fmaxf(mx0, m0); mn0 = fminf(mn0, m0);
                s1 += m1; q1 += m1 * m1; mx1 = fmaxf(mx1, m1); mn1 = fminf(mn1, m1);
                deg++;
            }
        }
        writeFeat(NN + j, lane, deg, s0, s1, q0, q1, mx0, mx1, mn0, mn1);
    }
}

// ------------------------- dual-threshold 3-pass radix select -------------
__global__ void k_sel2(int pass) {  // grid 157, block 256
    const int shift = (pass == 0) ? 21 : (pass == 1) ? 10 : 0;
    const unsigned nb = (pass == 2) ? 1024u : 2048u;
    int i = blockIdx.x * blockDim.x + threadIdx.x;
    unsigned prefC = 0, prefW = 0;
    if (pass > 0) { prefC = g_prefixC; prefW = g_prefixW; }
    unsigned binC = 0xFFFFFFFFu, binW = 0xFFFFFFFFu, w = 0;
    if (i < NT) {
        unsigned key = f2key(g_score[i]);
        int lv = i - (i / NN) * NN;
        w = (unsigned)(g_ptr[lv + 1] - g_ptr[lv]);
        bool mC, mW;
        if (pass == 0) { mC = true; mW = true; }
        else if (pass == 1) { mC = ((key >> 21) == (prefC >> 21)); mW = ((key >> 21) == (prefW >> 21)); }
        else { mC = ((key >> 10) == (prefC >> 10)); mW = ((key >> 10) == (prefW >> 10)); }
        unsigned bb = (key >> shift) & (nb - 1u);
        if (mC) binC = bb;
        if (mW) binW = bb;
    }
    warpHistAdd(g_binsA, binC, 1, nb);
    warpHistAdd(g_binsB, binW, w, nb);
    __threadfence();
    __shared__ int lastf;
    if (threadIdx.x == 0) lastf = (atomicAdd(&g_ticket, 1) == (int)gridDim.x - 1);
    __syncthreads();
    if (!lastf) return;
    int t = threadIdx.x;
    __shared__ unsigned ss[256];
    __shared__ unsigned rBin, rKrem;
    __shared__ float sThr, sTw;
    const int chunk = (int)(nb >> 8);
    // count pick
    {
        unsigned loc[8]; unsigned s = 0;
        #pragma unroll
        for (int j = 0; j < 8; j++) { loc[j] = (j < chunk) ? g_binsA[t * chunk + j] : 0u; s += loc[j]; }
        ss[t] = s;
        __syncthreads();
        for (int off = 1; off < 256; off <<= 1) {
            unsigned v = (t + off < 256) ? ss[t + off] : 0u;
            __syncthreads();
            ss[t] += v;
            __syncthreads();
        }
        unsigned kk = (pass == 0) ? KS_N : g_kremC;
        unsigned cumTop = (t < 255) ? ss[t + 1] : 0u;
        if (cumTop < kk && cumTop + s >= kk) {
            unsigned c = cumTop;
            for (int j = chunk - 1; j >= 0; j--) {
                if (c + loc[j] >= kk) { rBin = (unsigned)(t * chunk + j); rKrem = kk - c; break; }
                c += loc[j];
            }
        }
        __syncthreads();
        if (t == 0) {
            unsigned npref = prefC | (rBin << shift);
            if (pass < 2) { g_prefixC = npref; g_kremC = rKrem; }
            else sThr = key2f(npref);
        }
        __syncthreads();
    }
    // weight pick
    {
        unsigned loc[8]; unsigned s = 0;
        #pragma unroll
        for (int j = 0; j < 8; j++) { loc[j] = (j < chunk) ? g_binsB[t * chunk + j] : 0u; s += loc[j]; }
        ss[t] = s;
        __syncthreads();
        for (int off = 1; off < 256; off <<= 1) {
            unsigned v = (t + off < 256) ? ss[t + off] : 0u;
            __syncthreads();
            ss[t] += v;
            __syncthreads();
        }
        unsigned kk = (pass == 0) ? ES_E : g_kremW;
        unsigned cumTop = (t < 255) ? ss[t + 1] : 0u;
        if (cumTop < kk && cumTop + s >= kk) {
            unsigned c = cumTop;
            for (int j = chunk - 1; j >= 0; j--) {
                if (c + loc[j] >= kk) { rBin = (unsigned)(t * chunk + j); rKrem = kk - c; break; }
                c += loc[j];
            }
        }
        __syncthreads();
        if (t == 0) {
            unsigned npref = prefW | (rBin << shift);
            if (pass < 2) { g_prefixW = npref; g_kremW = rKrem; }
            else sTw = key2f(npref);
        }
        __syncthreads();
    }
    #pragma unroll
    for (int j = 0; j < 8; j++)
        if (j < chunk) { g_binsA[t * chunk + j] = 0; g_binsB[t * chunk + j] = 0; }
    if (t == 0) {
        g_ticket = 0;
        if (pass == 2) { g_thr = sThr; g_T = fmaxf(sThr, sTw); g_wl = 0; }
    }
}

// Layers 1-2: fused worklist + exact agg.
__global__ void k_aggSel(const float* __restrict__ relw, int l) {
    int i = blockIdx.x * 8 + (threadIdx.x >> 5);   // grid 5000
    if (i >= NT) return;
    int lane = threadIdx.x & 31;
    int base = (i / NN) * NN;
    int lv = i - base;
    int p0 = g_ptr[lv], p1 = g_ptr[lv + 1];
    float T = g_T;
    if (p1 == p0 || !(g_score[i] >= T)) return;
    int row = 0;
    if (lane == 0) row = atomicAdd(&g_wl, 1);
    row = __shfl_sync(0xffffffffu, row, 0);
    int d0 = lane, d1 = lane + 32;
    const float* rw = relw + l * 400 * DD;
    float s0 = 0, s1 = 0, q0 = 0, q1 = 0;
    float mx0 = -INFINITY, mx1 = -INFINITY, mn0 = INFINITY, mn1 = INFINITY;
    int deg = 0;
    for (int p = p0; p < p1; p++) {
        int pk = __ldg(&g_adj[p]);
        int u = pk & 0xFFFF, a = pk >> 16;
        int gu = base + u;
        float sc = g_score[gu];
        if (sc >= T) {
            float wgt = 1.0f / (1.0f + __expf(-sc));
            float m0 = wgt * g_hidden[(size_t)gu * DD + d0] * rw[a * DD + d0];
            float m1 = wgt * g_hidden[(size_t)gu * DD + d1] * rw[a * DD + d1];
            s0 += m0; q0 += m0 * m0; mx0 = fmaxf(mx0, m0); mn0 = fminf(mn0, m0);
            s1 += m1; q1 += m1 * m1; mx1 = fmaxf(mx1, m1); mn1 = fminf(mn1, m1);
            deg++;
        }
    }
    writeFeat(row, lane, deg, s0, s1, q0, q1, mx0, mx1, mn0, mn1);
    if (lane == 0) g_wlist[row] = i;
}

// C[cnt,192] = feat[cnt,256] @ Wcat[256,192]; 128x64 tile, 8x4 micro-tile
__global__ void k_gemm(int l) {
    __shared__ float sA[16 * 128];
    __shared__ float sB[16 * 64];
    int cnt = g_wl;
    int rowBase = blockIdx.x * 128;
    if (rowBase >= cnt) return;
    int colBase = blockIdx.y * 64;
    int t = threadIdx.x;
    int tx = t & 15, ty = t >> 4;
    const float* Wb = g_Wcat + l * 256 * 192;
    float acc[8][4] = {};
    for (int k0 = 0; k0 < 256; k0 += 16) {
        #pragma unroll
        for (int q = 0; q < 2; q++) {
            int lin = t * 2 + q;
            int r = lin >> 2, kq = lin & 3;
            float4 av = make_float4(0, 0, 0, 0);
            int row = rowBase + r;
            if (row < cnt) av = *(const float4*)(g_feat + (size_t)row * 256 + k0 + kq * 4);
            sA[(kq * 4 + 0) * 128 + r] = av.x;
            sA[(kq * 4 + 1) * 128 + r] = av.y;
            sA[(kq * 4 + 2) * 128 + r] = av.z;
            sA[(kq * 4 + 3) * 128 + r] = av.w;
        }
        {
            int kb = t >> 4, j4 = (t & 15) * 4;
            float4 bv = *(const float4*)(Wb + (size_t)(k0 + kb) * 192 + colBase + j4);
            *(float4*)&sB[kb * 64 + j4] = bv;
        }
        __syncthreads();
        #pragma unroll
        for (int kk = 0; kk < 16; kk++) {
            float4 a0 = *(float4*)&sA[kk * 128 + ty * 8];
            float4 a1 = *(float4*)&sA[kk * 128 + ty * 8 + 4];
            float4 b0 = *(float4*)&sB[kk * 64 + tx * 4];
            float a[8] = {a0.x, a0.y, a0.z, a0.w, a1.x, a1.y, a1.z, a1.w};
            float bb[4] = {b0.x, b0.y, b0.z, b0.w};
            #pragma unroll
            for (int i = 0; i < 8; i++)
                #pragma unroll
                for (int j = 0; j < 4; j++)
                    acc[i][j] += a[i] * bb[j];
        }
        __syncthreads();
    }
    #pragma unroll
    for (int i = 0; i < 8; i++) {
        int row = rowBase + ty * 8 + i;
        if (row < cnt) {
            float4 v = make_float4(acc[i][0], acc[i][1], acc[i][2], acc[i][3]);
            *(float4*)(g_C + (size_t)row * 192 + colBase + tx * 4) = v;
        }
    }
}

// Generic fused post (layers 1-2)
__global__ void k_post(const float* __restrict__ convb,
                       const float* __restrict__ Wlin,
                       const float* __restrict__ W1,
                       const float* __restrict__ b1,
                       const float* __restrict__ W2,
                       const float* __restrict__ b2, int l) {
    extern __shared__ float smem[];
    float* sh   = smem;
    float* sbuf = smem + 64 * 65;
    float* sqp  = sbuf + 64 * 128;
    float* samp = sqp + 64;
    float* satt = samp + 64;
    float* sw2  = satt + 64;
    float* sb1  = sw2 + 128;
    int*   sv   = (int*)(sb1 + 128);

    int cnt = g_wl;
    int rowBase = blockIdx.x * 64;
    if (rowBase >= cnt) return;
    int t = threadIdx.x;

    if (t < 64) {
        int i = rowBase + t;
        float dg = (i < cnt) ? g_deg[i] : 0.0f;
        float sl = logf(dg + 1.0f);
        float pna = g_pna;
        samp[t] = sl / pna;
        satt[t] = pna / (sl + 1e-6f);
        sv[t] = (i < cnt) ? g_wlist[i] : -1;
        sqp[t] = g_qpart[t];
    }
    if (t < 128) { sw2[t] = W2[t]; sb1[t] = b1[t]; }
    __syncthreads();

    #pragma unroll
    for (int q = 0; q < 16; q++) {
        int lin = t + q * 256;
        int r = lin >> 6, d = lin & 63;
        int i = rowBase + r;
        float nh = 0.0f;
        if (i < cnt) {
            const float* C = g_C + (size_t)i * 192;
            float u = C[d] + samp[r] * C[64 + d] + satt[r] * C[128 + d] + convb[l * 64 + d];
            u = fmaxf(u, 0.0f);
            int v = sv[r];
            nh = g_hidden[(size_t)v * DD + d] + u;
            g_hidden[(size_t)v * DD + d] = nh;
        }
        sh[r * 65 + d] = nh;
    }
    #pragma unroll
    for (int q = 0; q < 16; q++) {
        int lin = t + q * 256;
        int r = lin >> 6, c = lin & 63;
        sbuf[r * 68 + c] = Wlin[r * DD + c];
    }
    __syncthreads();

    int tx = t & 15, ty = t >> 4;
    {
        float acc[4][4] = {};
        for (int k = 0; k < 64; k++) {
            float a[4], bb[4];
            #pragma unroll
            for (int i = 0; i < 4; i++) a[i] = sh[(ty * 4 + i) * 65 + k];
            float4 b4 = *(float4*)&sbuf[k * 68 + tx * 4];
            bb[0] = b4.x; bb[1] = b4.y; bb[2] = b4.z; bb[3] = b4.w;
            #pragma unroll
            for (int i = 0; i < 4; i++)
                #pragma unroll
                for (int j = 0; j < 4; j++)
                    acc[i][j] += a[i] * bb[j];
        }
        __syncthreads();
        #pragma unroll
        for (int i = 0; i < 4; i++)
            #pragma unroll
            for (int j = 0; j < 4; j++) {
                int r = ty * 4 + i, c = tx * 4 + j;
                float hv = sh[r * 65 + c];
                sh[r * 65 + c] = hv * (acc[i][j] + sqp[c]);
            }
        __syncthreads();
    }

    #pragma unroll
    for (int q = 0; q < 32; q++) {
        int lin = t + q * 256;
        sbuf[lin] = W1[lin];
    }
    __syncthreads();

    {
        float acc[4][8] = {};
        for (int k = 0; k < 64; k++) {
            float a[4];
            #pragma unroll
            for (int i = 0; i < 4; i++) a[i] = sh[(ty * 4 + i) * 65 + k];
            float4 b0 = *(float4*)&sbuf[k * 128 + tx * 8];
            float4 b1v = *(float4*)&sbuf[k * 128 + tx * 8 + 4];
            float bb[8] = {b0.x, b0.y, b0.z, b0.w, b1v.x, b1v.y, b1v.z, b1v.w};
            #pragma unroll
            for (int i = 0; i < 4; i++)
                #pragma unroll
                for (int j = 0; j < 8; j++)
                    acc[i][j] += a[i] * bb[j];
        }
        float bias2 = b2[0];
        #pragma unroll
        for (int i = 0; i < 4; i++) {
            float p = 0.0f;
            #pragma unroll
            for (int j = 0; j < 8; j++) {
                int o = tx * 8 + j;
                p += fmaxf(acc[i][j] + sb1[o], 0.0f) * sw2[o];
            }
            p += __shfl_xor_sync(0xffffffffu, p, 1);
            p += __shfl_xor_sync(0xffffffffu, p, 2);
            p += __shfl_xor_sync(0xffffffffu, p, 4);
            p += __shfl_xor_sync(0xffffffffu, p, 8);
            if ((t & 15) == 0) {
                int i2 = rowBase + ty * 4 + i;
                if (i2 < cnt) {
                    int v = sv[ty * 4 + i];
                    g_score[v] = p + bias2;
                }
            }
        }
    }
}

// Layer-0 post + broadcast: blocks [0,165) post0; [165,2040) bcast copies 1-3.
__global__ void k_post0x(const float* __restrict__ text,
                         const float* __restrict__ convb,
                         const float* __restrict__ Wlin,
                         const float* __restrict__ W1,
                         const float* __restrict__ b1,
                         const float* __restrict__ W2,
                         const float* __restrict__ b2) {
    int t = threadIdx.x;
    if (blockIdx.x >= 165) {
        int idx = (blockIdx.x - 165) * 256 + t;    // [0, 3*NN*16)
        if (idx >= 3 * NN * 16) return;
        int v = NN + (idx >> 4), q = idx & 15;
        if (g_dirty[v]) return;
        int lv = v - (v / NN) * NN;
        int deg = g_ptr[lv + 1] - g_ptr[lv];
        if (deg <= 0) return;
        int dc = min(deg, 255);
        float4 uv = *(const float4*)(g_updB + dc * 64 + q * 4);
        *(float4*)(g_hidden + (size_t)v * DD + q * 4) = uv;
        if (q == 0) g_score[v] = g_scoreB[dc];
        return;
    }
    extern __shared__ float smem[];
    float* sh   = smem;
    float* sbuf = smem + 64 * 65;
    float* sqp  = sbuf + 64 * 128;
    float* samp = sqp + 64;
    float* satt = samp + 64;
    float* sw2  = satt + 64;
    float* sb1  = sw2 + 128;
    int*   svg  = (int*)(sb1 + 128);
    int*   som  = svg + 64;   // bit0 omask, bit1 isbase(copy0), bit2 copy0-dirty

    int cnt = g_wl;
    int rowBase = blockIdx.x * 64;
    if (rowBase >= cnt) return;

    if (t < 64) {
        int i = rowBase + t;
        float dg = 0.0f; int vg = 0; int flags = 0;
        if (i < cnt) {
            dg = g_deg[i];
            if (i < NN) {
                vg = i;
                flags = 2 | ((g_ptr[i + 1] > g_ptr[i]) ? 1 : 0) | (g_dirty[i] ? 4 : 0);
            } else {
                int v = g_dlist[i - NN]; vg = v;
                int lv = v - (v / NN) * NN;
                int sdeg = g_ptr[lv + 1] - g_ptr[lv];
                flags = ((g_score[v] >= 0.0f) && sdeg > 0) ? 1 : 0;
            }
        }
        float sl = logf(dg + 1.0f);
        float pna = g_pna;
        samp[t] = sl / pna;
        satt[t] = pna / (sl + 1e-6f);
        svg[t] = vg; som[t] = flags;
        sqp[t] = g_qpart[t];
    }
    if (t < 128) { sw2[t] = W2[t]; sb1[t] = b1[t]; }
    __syncthreads();

    #pragma unroll
    for (int q = 0; q < 16; q++) {
        int lin = t + q * 256;
        int r = lin >> 6, d = lin & 63;
        int i = rowBase + r;
        float nh = 0.0f;
        if (i < cnt) {
            int flags = som[r]; int vg = svg[r];
            float pre = (flags & 2) ? text[(size_t)vg * DD + d]
                                    : g_hidden[(size_t)vg * DD + d];
            float u = 0.0f;
            if (flags & 1) {
                const float* C = g_C + (size_t)i * 192;
                u = fmaxf(C[d] + samp[r] * C[64 + d] + satt[r] * C[128 + d] + convb[d], 0.0f);
            }
            nh = pre + u;
            if (flags & 2) {
                if (!(flags & 4)) g_hidden[(size_t)vg * DD + d] = nh;  // copy 0 only
            } else {
                g_hidden[(size_t)vg * DD + d] = nh;
            }
        }
        sh[r * 65 + d] = nh;
    }
    #pragma unroll
    for (int q = 0; q < 16; q++) {
        int lin = t + q * 256;
        int r = lin >> 6, c = lin & 63;
        sbuf[r * 68 + c] = Wlin[r * DD + c];
    }
    __syncthreads();

    int tx = t & 15, ty = t >> 4;
    {
        float acc[4][4] = {};
        for (int k = 0; k < 64; k++) {
            float a[4], bb[4];
            #pragma unroll
            for (int i = 0; i < 4; i++) a[i] = sh[(ty * 4 + i) * 65 + k];
            float4 b4 = *(float4*)&sbuf[k * 68 + tx * 4];
            bb[0] = b4.x; bb[1] = b4.y; bb[2] = b4.z; bb[3] = b4.w;
            #pragma unroll
            for (int i = 0; i < 4; i++)
                #pragma unroll
                for (int j = 0; j < 4; j++)
                    acc[i][j] += a[i] * bb[j];
        }
        __syncthreads();
        #pragma unroll
        for (int i = 0; i < 4; i++)
            #pragma unroll
            for (int j = 0; j < 4; j++) {
                int r = ty * 4 + i, c = tx * 4 + j;
                float hv = sh[r * 65 + c];
                sh[r * 65 + c] = hv * (acc[i][j] + sqp[c]);
            }
        __syncthreads();
    }

    #pragma unroll
    for (int q = 0; q < 32; q++) {
        int lin = t + q * 256;
        sbuf[lin] = W1[lin];
    }
    __syncthreads();

    {
        float acc[4][8] = {};
        for (int k = 0; k < 64; k++) {
            float a[4];
            #pragma unroll
            for (int i = 0; i < 4; i++) a[i] = sh[(ty * 4 + i) * 65 + k];
            float4 b0 = *(float4*)&sbuf[k * 128 + tx * 8];
            float4 b1v = *(float4*)&sbuf[k * 128 + tx * 8 + 4];
            float bb[8] = {b0.x, b0.y, b0.z, b0.w, b1v.x, b1v.y, b1v.z, b1v.w};
            #pragma unroll
            for (int i = 0; i < 4; i++)
                #pragma unroll
                for (int j = 0; j < 8; j++)
                    acc[i][j] += a[i] * bb[j];
        }
        float bias2 = b2[0];
        #pragma unroll
        for (int i = 0; i < 4; i++) {
            float p = 0.0f;
            #pragma unroll
            for (int j = 0; j < 8; j++) {
                int o = tx * 8 + j;
                p += fmaxf(acc[i][j] + sb1[o], 0.0f) * sw2[o];
            }
            p += __shfl_xor_sync(0xffffffffu, p, 1);
            p += __shfl_xor_sync(0xffffffffu, p, 2);
            p += __shfl_xor_sync(0xffffffffu, p, 4);
            p += __shfl_xor_sync(0xffffffffu, p, 8);
            if ((t & 15) == 0) {
                int i2 = rowBase + ty * 4 + i;
                if (i2 < cnt) {
                    int flags = som[ty * 4 + i];
                    int vg = svg[ty * 4 + i];
                    float sc = p + bias2;
                    if (flags & 2) {
                        if ((flags & 1) && !(flags & 4)) g_score[vg] = sc;
                    } else if (flags & 1) {
                        g_score[vg] = sc;
                    }
                }
            }
        }
    }
}

__global__ void k_out(const int* __restrict__ t_index, float* __restrict__ out) {
    int t = threadIdx.x;
    if (t >= 64) return;
    int b = t / 16;
    int v = t_index[t] + b * NN;
    out[t] = g_score[v];
}

// ------------------------- launch -------------------------
extern "C" void kernel_launch(void* const* d_in, const int* in_sizes, int n_in,
                              void* d_out, int out_size) {
    const int*   h_index   = (const int*)d_in[0];
    const int*   r_index   = (const int*)d_in[1];
    const int*   t_index   = (const int*)d_in[2];
    const float* hstates   = (const float*)d_in[3];
    const int*   edge_idx  = (const int*)d_in[5];
    const int*   edge_attr = (const int*)d_in[6];
    const float* text      = (const float*)d_in[7];
    const float* relT      = (const float*)d_in[9];
    const float* Wlin      = (const float*)d_in[10];
    const float* blin      = (const float*)d_in[11];
    const float* W1        = (const float*)d_in[12];
    const float* b1        = (const float*)d_in[13];
    const float* W2        = (const float*)d_in[14];
    const float* b2        = (const float*)d_in[15];
    const float* relw      = (const float*)d_in[16];
    const float* convW     = (const float*)d_in[17];
    const float* convb     = (const float*)d_in[18];
    float* out = (float*)d_out;

    const int SMEM_POST  = (64 * 65 + 64 * 128 + 64 * 3 + 128 * 2 + 64) * 4;
    const int SMEM_POST0 = (64 * 65 + 64 * 128 + 64 * 3 + 128 * 2 + 128) * 4;
    static int attr_done = 0;
    if (!attr_done) {
        cudaFuncSetAttribute(k_post, cudaFuncAttributeMaxDynamicSharedMemorySize, SMEM_POST);
        cudaFuncSetAttribute(k_post0x, cudaFuncAttributeMaxDynamicSharedMemorySize, SMEM_POST0);
        attr_done = 1;
    }

    k_setup<<<3234, 256>>>(text, h_index, hstates, convW);
    k_count<<<391, 256>>>(edge_idx);
    k_scanA<<<40, 256>>>();
    k_scan<<<1, 1024>>>();
    k_scatter<<<391, 256>>>(edge_idx, edge_attr);
    k_prep<<<259, 128>>>(h_index, r_index, hstates, relT, Wlin, blin, W1, b1, W2, b2, convb);

    // ---- layer 0 (thr = T = 0 statically) ----
    k_agg0<<<1314, 256>>>(text, relw);
    k_gemm<<<dim3(83, 3), 256>>>(0);
    k_post0x<<<2040, 256, SMEM_POST0>>>(text, convb, Wlin, W1, b1, W2, b2);

    // ---- layers 1-2 ----
    for (int l = 1; l < 3; l++) {
        k_sel2<<<157, 256>>>(0);
        k_sel2<<<157, 256>>>(1);
        k_sel2<<<157, 256>>>(2);   // tail sets g_thr, g_T, resets g_wl
        k_aggSel<<<5000, 256>>>(relw, l);
        k_gemm<<<dim3(64, 3), 256>>>(l);
        k_post<<<128, 256, SMEM_POST>>>(convb, Wlin, W1, b1, W2, b2, l);
    }
    k_out<<<1, 64>>>(t_index, out);
}